// round 1
// baseline (speedup 1.0000x reference)
#include <cuda_runtime.h>
#include <math.h>

// ---------------- problem constants (fixed shapes) ----------------
// B=16, L=4096 (H=W=64), C=512, Cr=128, heads=8, hd=64, sr=4
// x_dwt: (B,512,32,32), kv tokens: B*64=1024, Lk=64

#define NB 16
#define LTOK 4096
#define CDIM 512
#define CRDIM 128
#define OUT_ELEMS 33554432   // 16*4096*512
// attn elems: 16*8*4096*64 = 33554432

// ---------------- scratch (__device__ globals; no allocs) ----------------
static __device__ float g_q[33554432];      // (B*L, 512)  q * scale
static __device__ float g_xred[8388608];    // (B,64,64,128) token-major
static __device__ float g_dwt1[8388608];    // (B,32,32,512) pixel-major, ch = f*128+c
static __device__ float g_dwt2[8388608];    // (B,32,32,512) after conv3x3+bn2+relu
static __device__ float g_wconv[2359296];   // (512, 9*512) filt_w permuted to (o, tap*512+c)
static __device__ float g_im2col[8388608];  // (1024, 8192)
static __device__ float g_kvtok[524288];    // (1024, 512)
static __device__ float g_ln[524288];       // (1024, 512)
static __device__ float g_kv[1048576];      // (1024, 1024)
static __device__ float g_aproj[41943040];  // (65536, 640): [0:512) attn out, [512:640) idwt
static __device__ float g_sc1[128], g_sh1[128];
static __device__ float g_sc2[512], g_sh2[512];

// ---------------- bn precompute: s = g*rsqrt(v+eps), sh = beta - m*s + bias*s ----
__global__ void bnprep_k(const float* __restrict__ g, const float* __restrict__ be,
                         const float* __restrict__ mu, const float* __restrict__ va,
                         const float* __restrict__ bias, float* __restrict__ sc,
                         float* __restrict__ sh, int n)
{
    int i = blockIdx.x * blockDim.x + threadIdx.x;
    if (i < n) {
        float s = g[i] * rsqrtf(va[i] + 1e-5f);
        sc[i] = s;
        sh[i] = be[i] - mu[i] * s + bias[i] * s;
    }
}

// ---------------- filt_w remap: (o, c, tap) -> (o, tap*512 + c) --------------
__global__ void wremap_k(const float* __restrict__ fw, float* __restrict__ wout)
{
    int idx = blockIdx.x * blockDim.x + threadIdx.x;   // 512*4608
    if (idx >= 512 * 4608) return;
    int o = idx / 4608;
    int k = idx - o * 4608;
    int tap = k >> 9;
    int c = k & 511;
    wout[idx] = fw[o * 4608 + c * 9 + tap];
}

// ---------------- generic SGEMM: C[M,N] = epi(A[M,K] @ B[N,K]^T) --------------
// EPI 0: alpha*(acc + bias[n]);  EPI 1: relu(acc*sc[n] + sh[n])
// CONV 1: A is implicit im2col of g_dwt1 (B,32,32,512) with 3x3 pad-1 taps.
template<int EPI, int CONV>
__global__ void __launch_bounds__(256, 2)
gemm_k(const float* __restrict__ A, const float* __restrict__ Bm,
       const float* __restrict__ bias, const float* __restrict__ sc,
       const float* __restrict__ sh, float* __restrict__ C,
       int M, int N, int K, float alpha)
{
    __shared__ float As[8][128];
    __shared__ float Bs[8][128];
    const int tid = threadIdx.x;
    const int bm = blockIdx.y * 128;
    const int bn = blockIdx.x * 128;
    const int tx = tid & 15;
    const int ty = tid >> 4;
    const int lrow = tid >> 1;
    const int lcol = (tid & 1) * 4;

    float acc[8][8];
#pragma unroll
    for (int i = 0; i < 8; i++)
#pragma unroll
        for (int j = 0; j < 8; j++) acc[i][j] = 0.f;

    int cb = 0, cy = 0, cx = 0;
    if (CONV) {
        int m = bm + lrow;
        cb = m >> 10;
        int p = m & 1023;
        cy = p >> 5;
        cx = p & 31;
    }
    const float* aptr = A + (long)(bm + lrow) * K + lcol;
    const float* bptr = Bm + (long)(bn + lrow) * K + lcol;

    for (int k0 = 0; k0 < K; k0 += 8) {
        float4 av;
        if (!CONV) {
            av = *(const float4*)(aptr + k0);
        } else {
            int tap = k0 >> 9;
            int dy = tap / 3 - 1, dx = tap - (tap / 3) * 3 - 1;
            int yy = cy + dy, xx = cx + dx;
            int c = (k0 & 511) + lcol;
            if ((unsigned)yy < 32u && (unsigned)xx < 32u)
                av = *(const float4*)(A + (((long)((cb * 32 + yy) * 32 + xx)) << 9) + c);
            else
                av = make_float4(0.f, 0.f, 0.f, 0.f);
        }
        float4 bv = *(const float4*)(bptr + k0);
        As[lcol + 0][lrow] = av.x; As[lcol + 1][lrow] = av.y;
        As[lcol + 2][lrow] = av.z; As[lcol + 3][lrow] = av.w;
        Bs[lcol + 0][lrow] = bv.x; Bs[lcol + 1][lrow] = bv.y;
        Bs[lcol + 2][lrow] = bv.z; Bs[lcol + 3][lrow] = bv.w;
        __syncthreads();
#pragma unroll
        for (int kk = 0; kk < 8; kk++) {
            float ar[8], br[8];
#pragma unroll
            for (int i = 0; i < 8; i++) ar[i] = As[kk][ty * 8 + i];
#pragma unroll
            for (int j = 0; j < 8; j++) br[j] = Bs[kk][tx * 8 + j];
#pragma unroll
            for (int i = 0; i < 8; i++)
#pragma unroll
                for (int j = 0; j < 8; j++)
                    acc[i][j] = fmaf(ar[i], br[j], acc[i][j]);
        }
        __syncthreads();
    }

#pragma unroll
    for (int i = 0; i < 8; i++) {
        int row = bm + ty * 8 + i;
#pragma unroll
        for (int j = 0; j < 8; j++) {
            int col = bn + tx * 8 + j;
            float v = acc[i][j];
            if (EPI == 0) v = alpha * (v + bias[col]);
            else          v = fmaxf(v * sc[col] + sh[col], 0.f);
            C[(long)row * N + col] = v;
        }
    }
}

// ---------------- Haar DWT: xred (B,64,64,128) -> dwt1 (B,32,32,512) ----------
__global__ void dwt_k(const float* __restrict__ xr, float* __restrict__ o)
{
    int idx = blockIdx.x * 256 + threadIdx.x;   // 16384 pos * 32 chan-quads
    int cq = idx & 31;
    int pos = idx >> 5;
    int b = pos >> 10;
    int r = pos & 1023;
    int h = r >> 5, w = r & 31;
    const float* base = xr + ((long)((b * 64 + 2 * h) * 64 + 2 * w)) * 128 + cq * 4;
    float4 x00 = *(const float4*)(base);
    float4 x01 = *(const float4*)(base + 128);
    float4 x10 = *(const float4*)(base + 64 * 128);
    float4 x11 = *(const float4*)(base + 64 * 128 + 128);
    float4 ll, lh, hl, hh;
#define DWT1(f) \
    ll.f = 0.5f * (x00.f + x01.f + x10.f + x11.f); \
    lh.f = 0.5f * (x00.f + x01.f - x10.f - x11.f); \
    hl.f = 0.5f * (x00.f - x01.f + x10.f - x11.f); \
    hh.f = 0.5f * (x00.f - x01.f - x10.f + x11.f);
    DWT1(x) DWT1(y) DWT1(z) DWT1(w)
#undef DWT1
    float* op = o + (long)pos * 512 + cq * 4;
    *(float4*)(op)       = ll;
    *(float4*)(op + 128) = lh;
    *(float4*)(op + 256) = hl;
    *(float4*)(op + 384) = hh;
}

// ---------------- Haar IDWT: dwt2 (B,32,32,512) -> g_aproj cols [512,640) -----
__global__ void idwt_k(const float* __restrict__ d2, float* __restrict__ ap)
{
    int idx = blockIdx.x * 256 + threadIdx.x;
    int cq = idx & 31;
    int pos = idx >> 5;
    int b = pos >> 10;
    int r = pos & 1023;
    int h = r >> 5, w = r & 31;
    const float* ip = d2 + (long)pos * 512 + cq * 4;
    float4 ll = *(const float4*)(ip);
    float4 lh = *(const float4*)(ip + 128);
    float4 hl = *(const float4*)(ip + 256);
    float4 hh = *(const float4*)(ip + 384);
    float4 y00, y01, y10, y11;
#define IDWT1(f) \
    y00.f = 0.5f * (ll.f + lh.f + hl.f + hh.f); \
    y01.f = 0.5f * (ll.f + lh.f - hl.f - hh.f); \
    y10.f = 0.5f * (ll.f - lh.f + hl.f - hh.f); \
    y11.f = 0.5f * (ll.f - lh.f - hl.f + hh.f);
    IDWT1(x) IDWT1(y) IDWT1(z) IDWT1(w)
#undef IDWT1
    float* base = ap + ((long)(b * 4096 + (2 * h) * 64 + 2 * w)) * 640 + 512 + cq * 4;
    *(float4*)(base)                = y00;
    *(float4*)(base + 640)          = y01;
    *(float4*)(base + 64 * 640)       = y10;
    *(float4*)(base + 64 * 640 + 640) = y11;
}

// ---------------- im2col for kvq 4x4/s4 conv: (1024, 8192) -------------------
__global__ void im2col_k(const float* __restrict__ d2, float* __restrict__ col)
{
    int idx = blockIdx.x * 256 + threadIdx.x;   // 1024 * 2048 float4s
    if (idx >= 1024 * 2048) return;
    int t = idx >> 11;
    int k4 = (idx & 2047) * 4;
    int c = k4 >> 4;
    int ij = k4 & 15;
    int i = ij >> 2;        // float4 spans j=0..3
    int b = t >> 6;
    int pp = t & 63;
    int ph = pp >> 3, pw = pp & 7;
    int y = 4 * ph + i;
    int x0 = 4 * pw;
    const float* sp = d2 + ((long)((b * 32 + y) * 32 + x0)) * 512 + c;
    float4 v;
    v.x = sp[0]; v.y = sp[512]; v.z = sp[1024]; v.w = sp[1536];
    *(float4*)(col + (long)t * 8192 + k4) = v;
}

// ---------------- layernorm over 512 per row, 1024 rows ----------------------
__global__ void ln_k(const float* __restrict__ in, const float* __restrict__ g,
                     const float* __restrict__ be, float* __restrict__ out)
{
    int row = blockIdx.x;
    const float* p = in + (long)row * 512;
    int tid = threadIdx.x;   // 256
    float x0 = p[tid], x1 = p[tid + 256];
    float s = x0 + x1, q = x0 * x0 + x1 * x1;
    __shared__ float red[16];
    __shared__ float mv[2];
#pragma unroll
    for (int o = 16; o; o >>= 1) {
        s += __shfl_down_sync(0xffffffffu, s, o);
        q += __shfl_down_sync(0xffffffffu, q, o);
    }
    if ((tid & 31) == 0) { red[tid >> 5] = s; red[8 + (tid >> 5)] = q; }
    __syncthreads();
    if (tid == 0) {
        float S = 0.f, Q = 0.f;
        for (int i = 0; i < 8; i++) { S += red[i]; Q += red[8 + i]; }
        float mean = S * (1.f / 512.f);
        float var = Q * (1.f / 512.f) - mean * mean;
        mv[0] = mean;
        mv[1] = rsqrtf(var + 1e-5f);
    }
    __syncthreads();
    float mean = mv[0], inv = mv[1];
    out[(long)row * 512 + tid]       = (x0 - mean) * inv * g[tid] + be[tid];
    out[(long)row * 512 + tid + 256] = (x1 - mean) * inv * g[tid + 256] + be[tid + 256];
}

// ---------------- attention: Lk=64, one thread per query ---------------------
__global__ void __launch_bounds__(128)
attn_k(const float* __restrict__ qbuf, const float* __restrict__ kv,
       float* __restrict__ attn_out, float* __restrict__ proj_in)
{
    __shared__ float ks[64][65];
    __shared__ float vs[64][65];
    int b = blockIdx.x >> 3;
    int h = blockIdx.x & 7;
    int tid = threadIdx.x;
    for (int i = tid; i < 64 * 64; i += 128) {
        int t = i >> 6, d = i & 63;
        const float* kr = kv + (long)(b * 64 + t) * 1024 + h * 64;
        ks[t][d] = kr[d];
        vs[t][d] = kr[512 + d];
    }
    __syncthreads();
    int l = blockIdx.y * 128 + tid;
    long m = (long)b * 4096 + l;
    const float* qp = qbuf + m * 512 + h * 64;
    float qr[64];
#pragma unroll
    for (int d = 0; d < 64; d++) qr[d] = qp[d];   // q already scaled by hd^-0.5
    float s[64];
    float mx = -1e30f;
#pragma unroll
    for (int j = 0; j < 64; j++) {
        float a = 0.f;
#pragma unroll
        for (int d = 0; d < 64; d++) a = fmaf(qr[d], ks[j][d], a);
        s[j] = a;
        mx = fmaxf(mx, a);
    }
    float sum = 0.f;
#pragma unroll
    for (int j = 0; j < 64; j++) { s[j] = __expf(s[j] - mx); sum += s[j]; }
    float inv = 1.f / sum;
    float* ao = attn_out + (((long)(b * 8 + h) * 4096 + l) << 6);
#pragma unroll
    for (int j = 0; j < 64; j++) { s[j] *= inv; ao[j] = s[j]; }
    float* po = proj_in + m * 640 + h * 64;
#pragma unroll
    for (int d = 0; d < 64; d++) {
        float a = 0.f;
#pragma unroll
        for (int j = 0; j < 64; j++) a = fmaf(s[j], vs[j][d], a);
        po[d] = a;
    }
}

// ---------------- launch -----------------------------------------------------
static float* symaddr(const void* sym)
{
    void* p = nullptr;
    cudaGetSymbolAddress(&p, sym);
    return (float*)p;
}

extern "C" void kernel_launch(void* const* d_in, const int* in_sizes, int n_in,
                              void* d_out, int out_size)
{
    const float* x      = (const float*)d_in[0];
    const float* red_w  = (const float*)d_in[1];
    const float* red_b  = (const float*)d_in[2];
    const float* bn1_g  = (const float*)d_in[3];
    const float* bn1_b  = (const float*)d_in[4];
    const float* bn1_m  = (const float*)d_in[5];
    const float* bn1_v  = (const float*)d_in[6];
    const float* filt_w = (const float*)d_in[7];
    const float* filt_b = (const float*)d_in[8];
    const float* bn2_g  = (const float*)d_in[9];
    const float* bn2_b  = (const float*)d_in[10];
    const float* bn2_m  = (const float*)d_in[11];
    const float* bn2_v  = (const float*)d_in[12];
    const float* kvq_w  = (const float*)d_in[13];
    const float* kvq_b  = (const float*)d_in[14];
    const float* q_w    = (const float*)d_in[15];
    const float* q_b    = (const float*)d_in[16];
    const float* ln_g   = (const float*)d_in[17];
    const float* ln_b   = (const float*)d_in[18];
    const float* kv_w   = (const float*)d_in[19];
    const float* kv_b   = (const float*)d_in[20];
    const float* proj_w = (const float*)d_in[21];
    const float* proj_b = (const float*)d_in[22];

    float* out  = (float*)d_out;
    float* attn = out + OUT_ELEMS;

    float* p_q      = symaddr(g_q);
    float* p_xred   = symaddr(g_xred);
    float* p_dwt1   = symaddr(g_dwt1);
    float* p_dwt2   = symaddr(g_dwt2);
    float* p_wconv  = symaddr(g_wconv);
    float* p_im2col = symaddr(g_im2col);
    float* p_kvtok  = symaddr(g_kvtok);
    float* p_ln     = symaddr(g_ln);
    float* p_kv     = symaddr(g_kv);
    float* p_aproj  = symaddr(g_aproj);
    float* p_sc1    = symaddr(g_sc1);
    float* p_sh1    = symaddr(g_sh1);
    float* p_sc2    = symaddr(g_sc2);
    float* p_sh2    = symaddr(g_sh2);

    // prep
    bnprep_k<<<1, 128>>>(bn1_g, bn1_b, bn1_m, bn1_v, red_b, p_sc1, p_sh1, 128);
    bnprep_k<<<2, 256>>>(bn2_g, bn2_b, bn2_m, bn2_v, filt_b, p_sc2, p_sh2, 512);
    wremap_k<<<9216, 256>>>(filt_w, p_wconv);

    // q = (x @ q_w^T + q_b) * scale   (M=65536, N=512, K=512)
    gemm_k<0, 0><<<dim3(4, 512), 256>>>(x, q_w, q_b, nullptr, nullptr, p_q,
                                        65536, 512, 512, 0.125f);

    // xred = relu(bn1(x @ red_w^T + red_b))   (M=65536, N=128, K=512)
    gemm_k<1, 0><<<dim3(1, 512), 256>>>(x, red_w, nullptr, p_sc1, p_sh1, p_xred,
                                        65536, 128, 512, 1.f);

    // DWT
    dwt_k<<<2048, 256>>>(p_xred, p_dwt1);

    // conv3x3 + bn2 + relu  (implicit im2col GEMM: M=16384, N=512, K=4608)
    gemm_k<1, 1><<<dim3(4, 128), 256>>>(p_dwt1, p_wconv, nullptr, p_sc2, p_sh2,
                                        p_dwt2, 16384, 512, 4608, 1.f);

    // IDWT -> g_aproj cols [512,640)
    idwt_k<<<2048, 256>>>(p_dwt2, p_aproj);

    // kvq 4x4/s4 conv via im2col GEMM  (M=1024, N=512, K=8192)
    im2col_k<<<8192, 256>>>(p_dwt2, p_im2col);
    gemm_k<0, 0><<<dim3(4, 8), 256>>>(p_im2col, kvq_w, kvq_b, nullptr, nullptr,
                                      p_kvtok, 1024, 512, 8192, 1.f);

    // layernorm + kv GEMM (M=1024, N=1024, K=512)
    ln_k<<<1024, 256>>>(p_kvtok, ln_g, ln_b, p_ln);
    gemm_k<0, 0><<<dim3(8, 8), 256>>>(p_ln, kv_w, kv_b, nullptr, nullptr, p_kv,
                                      1024, 1024, 512, 1.f);

    // attention: writes attn output + g_aproj cols [0,512)
    attn_k<<<dim3(128, 32), 128>>>(p_q, p_kv, attn, p_aproj);

    // proj: (M=65536, N=512, K=640)
    gemm_k<0, 0><<<dim3(4, 512), 256>>>(p_aproj, proj_w, proj_b, nullptr, nullptr,
                                        out, 65536, 512, 640, 1.f);
}

// round 3
// speedup vs baseline: 2.1138x; 2.1138x over previous
#include <cuda_runtime.h>
#include <cuda_bf16.h>
#include <cstdint>
#include <math.h>

// ============================ PTX helpers (sm_80+ path; no tcgen05) =========
__device__ __forceinline__ uint32_t smem_u32(const void* p) {
    uint32_t a;
    asm("{ .reg .u64 t; cvta.to.shared.u64 t, %1; cvt.u32.u64 %0, t; }" : "=r"(a) : "l"(p));
    return a;
}
__device__ __forceinline__ void cp16(uint32_t dst, const void* src, int pred) {
    asm volatile("cp.async.cg.shared.global [%0], [%1], 16, %2;"
                 :: "r"(dst), "l"(src), "r"(pred ? 16 : 0) : "memory");
}
__device__ __forceinline__ void ldmx4(uint32_t* r, uint32_t addr) {
    asm volatile("ldmatrix.sync.aligned.m8n8.x4.shared.b16 {%0,%1,%2,%3}, [%4];"
                 : "=r"(r[0]), "=r"(r[1]), "=r"(r[2]), "=r"(r[3]) : "r"(addr));
}
__device__ __forceinline__ void hmma(float* d, const uint32_t* a, const uint32_t* b) {
    asm volatile("mma.sync.aligned.m16n8k16.row.col.f32.bf16.bf16.f32 "
                 "{%0,%1,%2,%3}, {%4,%5,%6,%7}, {%8,%9}, {%0,%1,%2,%3};"
                 : "+f"(d[0]), "+f"(d[1]), "+f"(d[2]), "+f"(d[3])
                 : "r"(a[0]), "r"(a[1]), "r"(a[2]), "r"(a[3]), "r"(b[0]), "r"(b[1]));
}

// ============================ scratch ============================
#define OUT_ELEMS 33554432
static __device__ float g_q[33554432];
static __device__ float g_xred[8388608];
static __device__ float g_dwt2[8388608];
static __device__ float g_kvtok[524288];
static __device__ float g_kv[1048576];
static __device__ float g_sc1[128], g_sh1[128], g_sc2[512], g_sh2[512];

static __device__ __nv_bfloat16 g_xh[33554432], g_xl[33554432];
static __device__ __nv_bfloat16 g_d1h[8388608],  g_d1l[8388608];
static __device__ __nv_bfloat16 g_aph[41943040], g_apl[41943040];
static __device__ __nv_bfloat16 g_lnh[524288],   g_lnl[524288];
static __device__ __nv_bfloat16 g_imh[8388608],  g_iml[8388608];
static __device__ __nv_bfloat16 g_qwh[262144],   g_qwl[262144];
static __device__ __nv_bfloat16 g_rwh[65536],    g_rwl[65536];
static __device__ __nv_bfloat16 g_cwh[2359296],  g_cwl[2359296];
static __device__ __nv_bfloat16 g_kqwh[4194304], g_kqwl[4194304];
static __device__ __nv_bfloat16 g_kvwh[524288],  g_kvwl[524288];
static __device__ __nv_bfloat16 g_pwh[327680],   g_pwl[327680];

// ============================ small helpers ============================
__device__ __forceinline__ void store_pair4(__nv_bfloat16* ph, __nv_bfloat16* pl, float4 v)
{
    __nv_bfloat16 hx = __float2bfloat16(v.x), hy = __float2bfloat16(v.y);
    __nv_bfloat16 hz = __float2bfloat16(v.z), hw = __float2bfloat16(v.w);
    ((__nv_bfloat162*)ph)[0] = __halves2bfloat162(hx, hy);
    ((__nv_bfloat162*)ph)[1] = __halves2bfloat162(hz, hw);
    __nv_bfloat16 lx = __float2bfloat16(v.x - __bfloat162float(hx));
    __nv_bfloat16 ly = __float2bfloat16(v.y - __bfloat162float(hy));
    __nv_bfloat16 lz = __float2bfloat16(v.z - __bfloat162float(hz));
    __nv_bfloat16 lw = __float2bfloat16(v.w - __bfloat162float(hw));
    ((__nv_bfloat162*)pl)[0] = __halves2bfloat162(lx, ly);
    ((__nv_bfloat162*)pl)[1] = __halves2bfloat162(lz, lw);
}

__global__ void cvt_k(const float* __restrict__ in, __nv_bfloat16* __restrict__ h,
                      __nv_bfloat16* __restrict__ l, int n)
{
    int i = (blockIdx.x * 256 + threadIdx.x) * 4;
    if (i >= n) return;
    store_pair4(h + i, l + i, *(const float4*)(in + i));
}

__global__ void bnprep_k(const float* __restrict__ g, const float* __restrict__ be,
                         const float* __restrict__ mu, const float* __restrict__ va,
                         const float* __restrict__ bias, float* __restrict__ sc,
                         float* __restrict__ sh, int n)
{
    int i = blockIdx.x * blockDim.x + threadIdx.x;
    if (i < n) {
        float s = g[i] * rsqrtf(va[i] + 1e-5f);
        sc[i] = s;
        sh[i] = be[i] - mu[i] * s + bias[i] * s;
    }
}

// filt_w (o,c,3,3) -> (o, tap*512+c), split into bf16 pairs
__global__ void wremap_k(const float* __restrict__ fw, __nv_bfloat16* __restrict__ wh,
                         __nv_bfloat16* __restrict__ wl)
{
    int idx = blockIdx.x * 256 + threadIdx.x;
    if (idx >= 512 * 4608) return;
    int o = idx / 4608;
    int k = idx - o * 4608;
    int tap = k >> 9, c = k & 511;
    float v = fw[o * 4608 + c * 9 + tap];
    __nv_bfloat16 h = __float2bfloat16(v);
    wh[idx] = h;
    wl[idx] = __float2bfloat16(v - __bfloat162float(h));
}

// ============================ tensor-core GEMM (mma.sync bf16 split) =========
// C[M,N] = epi(A[M,K] @ B[N,K]^T), A/B as bf16 (hi,lo) pairs; 3-product split.
// Tile 128x128, BK=32, 3-stage cp.async pipeline, 8 warps of 64x32.
// EPI 0: alpha*(acc+bias[n]);  EPI 1: relu(acc*sc[n]+sh[n])
// CONV 1: A gathered implicitly from (B,32,32,512) with 3x3 pad-1 taps.
#define TILE_B 10240            // 128 rows * 80 bytes (32 bf16 + 8 pad)
#define STAGE_B (4 * TILE_B)    // Ah, Al, Bh, Bl
#define SMEM_DYN (3 * STAGE_B)  // 122880

template<int EPI, int CONV>
__global__ void __launch_bounds__(256, 1)
tgemm_k(const __nv_bfloat16* __restrict__ Ah, const __nv_bfloat16* __restrict__ Al,
        const __nv_bfloat16* __restrict__ Bh, const __nv_bfloat16* __restrict__ Bl,
        const float* __restrict__ bias, const float* __restrict__ sc,
        const float* __restrict__ sh, float* __restrict__ C,
        int M, int N, int K, float alpha)
{
    extern __shared__ char smem[];
    const uint32_t sbase = smem_u32(smem);
    const int tid = threadIdx.x;
    const int wid = tid >> 5;
    const int lane = tid & 31;
    const int wm = wid >> 2;          // 0..1  (64-row slabs)
    const int wn = wid & 3;           // 0..3  (32-col slabs)
    const int bm = blockIdx.y << 7;
    const int bn = blockIdx.x << 7;

    const int nc = K >> 5;            // K-chunks of 32

    float acc[4][4][4];
#pragma unroll
    for (int i = 0; i < 4; i++)
#pragma unroll
        for (int j = 0; j < 4; j++)
#pragma unroll
            for (int r = 0; r < 4; r++) acc[i][j][r] = 0.f;

    auto fill = [&](int stage, int k0) {
        uint32_t sb = sbase + stage * STAGE_B;
        // 2048 cp16 ops: 4 tiles * 128 rows * 4 chunks
#pragma unroll
        for (int it = 0; it < 8; it++) {
            int g = it * 256 + tid;
            int t = g >> 9;           // 0=Ah 1=Al 2=Bh 3=Bl
            int s = g & 511;
            int r = s >> 2;
            int c4 = s & 3;
            uint32_t dst = sb + t * TILE_B + r * 80 + c4 * 16;
            if (t >= 2) {
                const __nv_bfloat16* src = (t == 2 ? Bh : Bl) + (long)(bn + r) * K + k0 + c4 * 8;
                cp16(dst, src, 1);
            } else if (!CONV) {
                const __nv_bfloat16* src = (t == 0 ? Ah : Al) + (long)(bm + r) * K + k0 + c4 * 8;
                cp16(dst, src, 1);
            } else {
                int m = bm + r;
                int cb = m >> 10, p = m & 1023, cy = p >> 5, cx = p & 31;
                int tap = k0 >> 9;
                int dy = tap / 3 - 1, dx = tap - (tap / 3) * 3 - 1;
                int yy = cy + dy, xx = cx + dx;
                int pred = ((unsigned)yy < 32u) && ((unsigned)xx < 32u);
                long off = pred ? (((long)((cb * 32 + yy) * 32 + xx)) << 9) + (k0 & 511) + c4 * 8 : 0;
                const __nv_bfloat16* src = (t == 0 ? Ah : Al) + off;
                cp16(dst, src, pred);
            }
        }
    };

    // prologue
    for (int s = 0; s < 3; s++) {
        if (s < nc) fill(s, s << 5);
        asm volatile("cp.async.commit_group;" ::: "memory");
    }

    // lane addressing for ldmatrix
    const int a_row = (lane & 15);
    const int a_kof = (lane >> 4) << 3;                 // 0 or 8
    const int b_row = (lane & 7) + ((lane >> 4) << 3);  // n within 16
    const int b_kof = ((lane >> 3) & 1) << 3;           // 0 or 8

    for (int c = 0; c < nc; c++) {
        asm volatile("cp.async.wait_group 2;" ::: "memory");
        __syncthreads();
        uint32_t sb = sbase + (c % 3) * STAGE_B;
        uint32_t pAh = sb + (wm * 64 + a_row) * 80 + a_kof * 2;
        uint32_t pAl = pAh + TILE_B;
        uint32_t pBh = sb + 2 * TILE_B + (wn * 32 + b_row) * 80 + b_kof * 2;
        uint32_t pBl = pBh + TILE_B;

#pragma unroll
        for (int ks = 0; ks < 2; ks++) {
            uint32_t ah[4][4], al[4][4], bh[2][4], bl[2][4];
#pragma unroll
            for (int mi = 0; mi < 4; mi++) {
                ldmx4(ah[mi], pAh + mi * 16 * 80 + ks * 32);
                ldmx4(al[mi], pAl + mi * 16 * 80 + ks * 32);
            }
#pragma unroll
            for (int nj = 0; nj < 2; nj++) {
                ldmx4(bh[nj], pBh + nj * 16 * 80 + ks * 32);
                ldmx4(bl[nj], pBl + nj * 16 * 80 + ks * 32);
            }
#pragma unroll
            for (int mi = 0; mi < 4; mi++)
#pragma unroll
                for (int ni = 0; ni < 4; ni++) {
                    const uint32_t* bhp = &bh[ni >> 1][(ni & 1) * 2];
                    const uint32_t* blp = &bl[ni >> 1][(ni & 1) * 2];
                    hmma(acc[mi][ni], ah[mi], bhp);
                    hmma(acc[mi][ni], ah[mi], blp);
                    hmma(acc[mi][ni], al[mi], bhp);
                }
        }
        __syncthreads();
        if (c + 3 < nc) fill(c % 3, (c + 3) << 5);
        asm volatile("cp.async.commit_group;" ::: "memory");
    }

    // epilogue
#pragma unroll
    for (int mi = 0; mi < 4; mi++) {
#pragma unroll
        for (int ni = 0; ni < 4; ni++) {
            int row = bm + wm * 64 + mi * 16 + (lane >> 2);
            int col = bn + wn * 32 + ni * 8 + (lane & 3) * 2;
            float2 e0, e1;
            if (EPI == 0) {
                float2 bv = *(const float2*)(bias + col);
                e0.x = alpha * (acc[mi][ni][0] + bv.x);
                e0.y = alpha * (acc[mi][ni][1] + bv.y);
                e1.x = alpha * (acc[mi][ni][2] + bv.x);
                e1.y = alpha * (acc[mi][ni][3] + bv.y);
            } else {
                float2 sv = *(const float2*)(sc + col);
                float2 hv = *(const float2*)(sh + col);
                e0.x = fmaxf(acc[mi][ni][0] * sv.x + hv.x, 0.f);
                e0.y = fmaxf(acc[mi][ni][1] * sv.y + hv.y, 0.f);
                e1.x = fmaxf(acc[mi][ni][2] * sv.x + hv.x, 0.f);
                e1.y = fmaxf(acc[mi][ni][3] * sv.y + hv.y, 0.f);
            }
            *(float2*)(C + (long)row * N + col) = e0;
            *(float2*)(C + (long)(row + 8) * N + col) = e1;
        }
    }
}

// ---------------- Haar DWT: xred (B,64,64,128) fp32 -> dwt1 bf16 pairs -------
__global__ void dwt_k(const float* __restrict__ xr, __nv_bfloat16* __restrict__ oh,
                      __nv_bfloat16* __restrict__ ol)
{
    int idx = blockIdx.x * 256 + threadIdx.x;
    int cq = idx & 31;
    int pos = idx >> 5;
    int b = pos >> 10;
    int r = pos & 1023;
    int h = r >> 5, w = r & 31;
    const float* base = xr + ((long)((b * 64 + 2 * h) * 64 + 2 * w)) * 128 + cq * 4;
    float4 x00 = *(const float4*)(base);
    float4 x01 = *(const float4*)(base + 128);
    float4 x10 = *(const float4*)(base + 64 * 128);
    float4 x11 = *(const float4*)(base + 64 * 128 + 128);
    float4 ll, lh, hl, hh;
#define DWT1(f) \
    ll.f = 0.5f * (x00.f + x01.f + x10.f + x11.f); \
    lh.f = 0.5f * (x00.f + x01.f - x10.f - x11.f); \
    hl.f = 0.5f * (x00.f - x01.f + x10.f - x11.f); \
    hh.f = 0.5f * (x00.f - x01.f - x10.f + x11.f);
    DWT1(x) DWT1(y) DWT1(z) DWT1(w)
#undef DWT1
    long o = (long)pos * 512 + cq * 4;
    store_pair4(oh + o,       ol + o,       ll);
    store_pair4(oh + o + 128, ol + o + 128, lh);
    store_pair4(oh + o + 256, ol + o + 256, hl);
    store_pair4(oh + o + 384, ol + o + 384, hh);
}

// ---------------- Haar IDWT: dwt2 fp32 -> aproj pairs cols [512,640) ---------
__global__ void idwt_k(const float* __restrict__ d2, __nv_bfloat16* __restrict__ aph,
                       __nv_bfloat16* __restrict__ apl)
{
    int idx = blockIdx.x * 256 + threadIdx.x;
    int cq = idx & 31;
    int pos = idx >> 5;
    int b = pos >> 10;
    int r = pos & 1023;
    int h = r >> 5, w = r & 31;
    const float* ip = d2 + (long)pos * 512 + cq * 4;
    float4 ll = *(const float4*)(ip);
    float4 lh = *(const float4*)(ip + 128);
    float4 hl = *(const float4*)(ip + 256);
    float4 hh = *(const float4*)(ip + 384);
    float4 y00, y01, y10, y11;
#define IDWT1(f) \
    y00.f = 0.5f * (ll.f + lh.f + hl.f + hh.f); \
    y01.f = 0.5f * (ll.f + lh.f - hl.f - hh.f); \
    y10.f = 0.5f * (ll.f - lh.f + hl.f - hh.f); \
    y11.f = 0.5f * (ll.f - lh.f - hl.f + hh.f);
    IDWT1(x) IDWT1(y) IDWT1(z) IDWT1(w)
#undef IDWT1
    long base = ((long)(b * 4096 + (2 * h) * 64 + 2 * w)) * 640 + 512 + cq * 4;
    store_pair4(aph + base,                apl + base,                y00);
    store_pair4(aph + base + 640,          apl + base + 640,          y01);
    store_pair4(aph + base + 64 * 640,       apl + base + 64 * 640,       y10);
    store_pair4(aph + base + 64 * 640 + 640, apl + base + 64 * 640 + 640, y11);
}

// ---------------- im2col for kvq conv -> bf16 pairs (1024, 8192) -------------
__global__ void im2col_k(const float* __restrict__ d2, __nv_bfloat16* __restrict__ ch,
                         __nv_bfloat16* __restrict__ cl)
{
    int idx = blockIdx.x * 256 + threadIdx.x;
    if (idx >= 1024 * 2048) return;
    int t = idx >> 11;
    int k4 = (idx & 2047) * 4;
    int c = k4 >> 4;
    int ij = k4 & 15;
    int i = ij >> 2;
    int b = t >> 6;
    int pp = t & 63;
    int ph = pp >> 3, pw = pp & 7;
    int y = 4 * ph + i;
    int x0 = 4 * pw;
    const float* sp = d2 + ((long)((b * 32 + y) * 32 + x0)) * 512 + c;
    float4 v;
    v.x = sp[0]; v.y = sp[512]; v.z = sp[1024]; v.w = sp[1536];
    store_pair4(ch + (long)t * 8192 + k4, cl + (long)t * 8192 + k4, v);
}

// ---------------- layernorm -> bf16 pairs ------------------------------------
__global__ void ln_k(const float* __restrict__ in, const float* __restrict__ g,
                     const float* __restrict__ be, __nv_bfloat16* __restrict__ oh,
                     __nv_bfloat16* __restrict__ ol)
{
    int row = blockIdx.x;
    const float* p = in + (long)row * 512;
    int tid = threadIdx.x;
    float x0 = p[tid], x1 = p[tid + 256];
    float s = x0 + x1, q = x0 * x0 + x1 * x1;
    __shared__ float red[16];
    __shared__ float mv[2];
#pragma unroll
    for (int o = 16; o; o >>= 1) {
        s += __shfl_down_sync(0xffffffffu, s, o);
        q += __shfl_down_sync(0xffffffffu, q, o);
    }
    if ((tid & 31) == 0) { red[tid >> 5] = s; red[8 + (tid >> 5)] = q; }
    __syncthreads();
    if (tid == 0) {
        float S = 0.f, Q = 0.f;
        for (int i = 0; i < 8; i++) { S += red[i]; Q += red[8 + i]; }
        float mean = S * (1.f / 512.f);
        float var = Q * (1.f / 512.f) - mean * mean;
        mv[0] = mean;
        mv[1] = rsqrtf(var + 1e-5f);
    }
    __syncthreads();
    float mean = mv[0], inv = mv[1];
    float v0 = (x0 - mean) * inv * g[tid] + be[tid];
    float v1 = (x1 - mean) * inv * g[tid + 256] + be[tid + 256];
    __nv_bfloat16 h0 = __float2bfloat16(v0), h1 = __float2bfloat16(v1);
    oh[(long)row * 512 + tid] = h0;
    oh[(long)row * 512 + tid + 256] = h1;
    ol[(long)row * 512 + tid] = __float2bfloat16(v0 - __bfloat162float(h0));
    ol[(long)row * 512 + tid + 256] = __float2bfloat16(v1 - __bfloat162float(h1));
}

// ---------------- attention: Lk=64 -------------------------------------------
__global__ void __launch_bounds__(128)
attn_k(const float* __restrict__ qbuf, const float* __restrict__ kv,
       float* __restrict__ attn_out, __nv_bfloat16* __restrict__ aph,
       __nv_bfloat16* __restrict__ apl)
{
    __shared__ float ks[64][65];
    __shared__ float vs[64][65];
    int b = blockIdx.x >> 3;
    int h = blockIdx.x & 7;
    int tid = threadIdx.x;
    for (int i = tid; i < 64 * 64; i += 128) {
        int t = i >> 6, d = i & 63;
        const float* kr = kv + (long)(b * 64 + t) * 1024 + h * 64;
        ks[t][d] = kr[d];
        vs[t][d] = kr[512 + d];
    }
    __syncthreads();
    int l = blockIdx.y * 128 + tid;
    long m = (long)b * 4096 + l;
    const float* qp = qbuf + m * 512 + h * 64;
    float qr[64];
#pragma unroll
    for (int d = 0; d < 64; d++) qr[d] = qp[d];
    float s[64];
    float mx = -1e30f;
#pragma unroll
    for (int j = 0; j < 64; j++) {
        float a = 0.f;
#pragma unroll
        for (int d = 0; d < 64; d++) a = fmaf(qr[d], ks[j][d], a);
        s[j] = a;
        mx = fmaxf(mx, a);
    }
    float sum = 0.f;
#pragma unroll
    for (int j = 0; j < 64; j++) { s[j] = __expf(s[j] - mx); sum += s[j]; }
    float inv = 1.f / sum;
    float* ao = attn_out + (((long)(b * 8 + h) * 4096 + l) << 6);
#pragma unroll
    for (int j = 0; j < 64; j++) { s[j] *= inv; ao[j] = s[j]; }
    __nv_bfloat16* poh = aph + m * 640 + h * 64;
    __nv_bfloat16* pol = apl + m * 640 + h * 64;
#pragma unroll
    for (int d = 0; d < 64; d += 2) {
        float a0 = 0.f, a1 = 0.f;
#pragma unroll
        for (int j = 0; j < 64; j++) {
            a0 = fmaf(s[j], vs[j][d], a0);
            a1 = fmaf(s[j], vs[j][d + 1], a1);
        }
        __nv_bfloat16 h0 = __float2bfloat16(a0), h1 = __float2bfloat16(a1);
        *(__nv_bfloat162*)(poh + d) = __halves2bfloat162(h0, h1);
        __nv_bfloat16 l0 = __float2bfloat16(a0 - __bfloat162float(h0));
        __nv_bfloat16 l1 = __float2bfloat16(a1 - __bfloat162float(h1));
        *(__nv_bfloat162*)(pol + d) = __halves2bfloat162(l0, l1);
    }
}

// ============================ launch =========================================
static void* symaddr_(const void* sym)
{
    void* p = nullptr;
    cudaGetSymbolAddress(&p, sym);
    return p;
}
#define SYM(T, name) T* name = (T*)symaddr_(g_##name)

extern "C" void kernel_launch(void* const* d_in, const int* in_sizes, int n_in,
                              void* d_out, int out_size)
{
    const float* x      = (const float*)d_in[0];
    const float* red_w  = (const float*)d_in[1];
    const float* red_b  = (const float*)d_in[2];
    const float* bn1_g  = (const float*)d_in[3];
    const float* bn1_b  = (const float*)d_in[4];
    const float* bn1_m  = (const float*)d_in[5];
    const float* bn1_v  = (const float*)d_in[6];
    const float* filt_w = (const float*)d_in[7];
    const float* filt_b = (const float*)d_in[8];
    const float* bn2_g  = (const float*)d_in[9];
    const float* bn2_b  = (const float*)d_in[10];
    const float* bn2_m  = (const float*)d_in[11];
    const float* bn2_v  = (const float*)d_in[12];
    const float* kvq_w  = (const float*)d_in[13];
    const float* kvq_b  = (const float*)d_in[14];
    const float* q_w    = (const float*)d_in[15];
    const float* q_b    = (const float*)d_in[16];
    const float* ln_g   = (const float*)d_in[17];
    const float* ln_b   = (const float*)d_in[18];
    const float* kv_w   = (const float*)d_in[19];
    const float* kv_b   = (const float*)d_in[20];
    const float* proj_w = (const float*)d_in[21];
    const float* proj_b = (const float*)d_in[22];

    float* out  = (float*)d_out;
    float* attn = out + OUT_ELEMS;

    SYM(float, q); SYM(float, xred); SYM(float, dwt2); SYM(float, kvtok); SYM(float, kv);
    SYM(float, sc1); SYM(float, sh1); SYM(float, sc2); SYM(float, sh2);
    SYM(__nv_bfloat16, xh);  SYM(__nv_bfloat16, xl);
    SYM(__nv_bfloat16, d1h); SYM(__nv_bfloat16, d1l);
    SYM(__nv_bfloat16, aph); SYM(__nv_bfloat16, apl);
    SYM(__nv_bfloat16, lnh); SYM(__nv_bfloat16, lnl);
    SYM(__nv_bfloat16, imh); SYM(__nv_bfloat16, iml);
    SYM(__nv_bfloat16, qwh); SYM(__nv_bfloat16, qwl);
    SYM(__nv_bfloat16, rwh); SYM(__nv_bfloat16, rwl);
    SYM(__nv_bfloat16, cwh); SYM(__nv_bfloat16, cwl);
    SYM(__nv_bfloat16, kqwh); SYM(__nv_bfloat16, kqwl);
    SYM(__nv_bfloat16, kvwh); SYM(__nv_bfloat16, kvwl);
    SYM(__nv_bfloat16, pwh); SYM(__nv_bfloat16, pwl);

    cudaFuncSetAttribute(tgemm_k<0, 0>, cudaFuncAttributeMaxDynamicSharedMemorySize, SMEM_DYN);
    cudaFuncSetAttribute(tgemm_k<1, 0>, cudaFuncAttributeMaxDynamicSharedMemorySize, SMEM_DYN);
    cudaFuncSetAttribute(tgemm_k<1, 1>, cudaFuncAttributeMaxDynamicSharedMemorySize, SMEM_DYN);

    // ---- prep ----
    bnprep_k<<<1, 128>>>(bn1_g, bn1_b, bn1_m, bn1_v, red_b, sc1, sh1, 128);
    bnprep_k<<<2, 256>>>(bn2_g, bn2_b, bn2_m, bn2_v, filt_b, sc2, sh2, 512);
    cvt_k<<<32768, 256>>>(x, xh, xl, 33554432);
    cvt_k<<<256, 256>>>(q_w, qwh, qwl, 262144);
    cvt_k<<<64, 256>>>(red_w, rwh, rwl, 65536);
    cvt_k<<<4096, 256>>>(kvq_w, kqwh, kqwl, 4194304);
    cvt_k<<<512, 256>>>(kv_w, kvwh, kvwl, 524288);
    cvt_k<<<320, 256>>>(proj_w, pwh, pwl, 327680);
    wremap_k<<<9216, 256>>>(filt_w, cwh, cwl);

    // ---- q = (x @ q_w^T + q_b) * 0.125 ----
    tgemm_k<0, 0><<<dim3(4, 512), 256, SMEM_DYN>>>(xh, xl, qwh, qwl, q_b, nullptr, nullptr,
                                                   q, 65536, 512, 512, 0.125f);
    // ---- xred = relu(bn1(x @ red_w^T)) ----
    tgemm_k<1, 0><<<dim3(1, 512), 256, SMEM_DYN>>>(xh, xl, rwh, rwl, nullptr, sc1, sh1,
                                                   xred, 65536, 128, 512, 1.f);
    // ---- DWT -> bf16 pairs ----
    dwt_k<<<2048, 256>>>(xred, d1h, d1l);
    // ---- conv3x3 + bn2 + relu (implicit im2col) ----
    tgemm_k<1, 1><<<dim3(4, 128), 256, SMEM_DYN>>>(d1h, d1l, cwh, cwl, nullptr, sc2, sh2,
                                                   dwt2, 16384, 512, 4608, 1.f);
    // ---- IDWT -> aproj pairs cols [512,640) ----
    idwt_k<<<2048, 256>>>(dwt2, aph, apl);
    // ---- kvq conv via im2col ----
    im2col_k<<<8192, 256>>>(dwt2, imh, iml);
    tgemm_k<0, 0><<<dim3(4, 8), 256, SMEM_DYN>>>(imh, iml, kqwh, kqwl, kvq_b, nullptr, nullptr,
                                                 kvtok, 1024, 512, 8192, 1.f);
    // ---- layernorm + kv GEMM ----
    ln_k<<<1024, 256>>>(kvtok, ln_g, ln_b, lnh, lnl);
    tgemm_k<0, 0><<<dim3(8, 8), 256, SMEM_DYN>>>(lnh, lnl, kvwh, kvwl, kv_b, nullptr, nullptr,
                                                 kv, 1024, 1024, 512, 1.f);
    // ---- attention: attn output + aproj pairs cols [0,512) ----
    attn_k<<<dim3(128, 32), 128>>>(q, kv, attn, aph, apl);
    // ---- proj ----
    tgemm_k<0, 0><<<dim3(4, 512), 256, SMEM_DYN>>>(aph, apl, pwh, pwl, proj_b, nullptr, nullptr,
                                                   out, 65536, 512, 640, 1.f);
}

// round 4
// speedup vs baseline: 2.1831x; 1.0328x over previous
#include <cuda_runtime.h>
#include <cuda_bf16.h>
#include <cstdint>
#include <math.h>

// ============================ PTX helpers (sm_80+ path) =====================
__device__ __forceinline__ uint32_t smem_u32(const void* p) {
    uint32_t a;
    asm("{ .reg .u64 t; cvta.to.shared.u64 t, %1; cvt.u32.u64 %0, t; }" : "=r"(a) : "l"(p));
    return a;
}
__device__ __forceinline__ void cp16(uint32_t dst, const void* src, int pred) {
    asm volatile("cp.async.cg.shared.global [%0], [%1], 16, %2;"
                 :: "r"(dst), "l"(src), "r"(pred ? 16 : 0) : "memory");
}
__device__ __forceinline__ void ldmx4(uint32_t* r, uint32_t addr) {
    asm volatile("ldmatrix.sync.aligned.m8n8.x4.shared.b16 {%0,%1,%2,%3}, [%4];"
                 : "=r"(r[0]), "=r"(r[1]), "=r"(r[2]), "=r"(r[3]) : "r"(addr));
}
__device__ __forceinline__ void hmma(float* d, const uint32_t* a, const uint32_t* b) {
    asm volatile("mma.sync.aligned.m16n8k16.row.col.f32.bf16.bf16.f32 "
                 "{%0,%1,%2,%3}, {%4,%5,%6,%7}, {%8,%9}, {%0,%1,%2,%3};"
                 : "+f"(d[0]), "+f"(d[1]), "+f"(d[2]), "+f"(d[3])
                 : "r"(a[0]), "r"(a[1]), "r"(a[2]), "r"(a[3]), "r"(b[0]), "r"(b[1]));
}

// ============================ scratch ============================
#define OUT_ELEMS 33554432
static __device__ float g_q[33554432];
static __device__ float g_xred[8388608];
static __device__ float g_dwt2[8388608];
static __device__ float g_kvtok[524288];
static __device__ float g_kv[1048576];
static __device__ float g_sc1[128], g_sh1[128], g_sc2[512], g_sh2[512];

static __device__ __nv_bfloat16 g_xh[33554432], g_xl[33554432];
static __device__ __nv_bfloat16 g_d1h[8388608],  g_d1l[8388608];
static __device__ __nv_bfloat16 g_aph[41943040], g_apl[41943040];
static __device__ __nv_bfloat16 g_lnh[524288],   g_lnl[524288];
static __device__ __nv_bfloat16 g_imh[8388608],  g_iml[8388608];
static __device__ __nv_bfloat16 g_qwh[262144],   g_qwl[262144];
static __device__ __nv_bfloat16 g_rwh[65536],    g_rwl[65536];
static __device__ __nv_bfloat16 g_cwh[2359296],  g_cwl[2359296];
static __device__ __nv_bfloat16 g_kqwh[4194304], g_kqwl[4194304];
static __device__ __nv_bfloat16 g_kvwh[524288],  g_kvwl[524288];
static __device__ __nv_bfloat16 g_pwh[327680],   g_pwl[327680];

// ============================ small helpers ============================
__device__ __forceinline__ void store_pair4(__nv_bfloat16* ph, __nv_bfloat16* pl, float4 v)
{
    __nv_bfloat16 hx = __float2bfloat16(v.x), hy = __float2bfloat16(v.y);
    __nv_bfloat16 hz = __float2bfloat16(v.z), hw = __float2bfloat16(v.w);
    ((__nv_bfloat162*)ph)[0] = __halves2bfloat162(hx, hy);
    ((__nv_bfloat162*)ph)[1] = __halves2bfloat162(hz, hw);
    __nv_bfloat16 lx = __float2bfloat16(v.x - __bfloat162float(hx));
    __nv_bfloat16 ly = __float2bfloat16(v.y - __bfloat162float(hy));
    __nv_bfloat16 lz = __float2bfloat16(v.z - __bfloat162float(hz));
    __nv_bfloat16 lw = __float2bfloat16(v.w - __bfloat162float(hw));
    ((__nv_bfloat162*)pl)[0] = __halves2bfloat162(lx, ly);
    ((__nv_bfloat162*)pl)[1] = __halves2bfloat162(lz, lw);
}

__global__ void cvt_k(const float* __restrict__ in, __nv_bfloat16* __restrict__ h,
                      __nv_bfloat16* __restrict__ l, int n)
{
    int i = (blockIdx.x * 256 + threadIdx.x) * 4;
    if (i >= n) return;
    store_pair4(h + i, l + i, *(const float4*)(in + i));
}

__global__ void bnprep_k(const float* __restrict__ g, const float* __restrict__ be,
                         const float* __restrict__ mu, const float* __restrict__ va,
                         const float* __restrict__ bias, float* __restrict__ sc,
                         float* __restrict__ sh, int n)
{
    int i = blockIdx.x * blockDim.x + threadIdx.x;
    if (i < n) {
        float s = g[i] * rsqrtf(va[i] + 1e-5f);
        sc[i] = s;
        sh[i] = be[i] - mu[i] * s + bias[i] * s;
    }
}

// filt_w (o,c,3,3) -> (o, tap*512+c), split into bf16 pairs
__global__ void wremap_k(const float* __restrict__ fw, __nv_bfloat16* __restrict__ wh,
                         __nv_bfloat16* __restrict__ wl)
{
    int idx = blockIdx.x * 256 + threadIdx.x;
    if (idx >= 512 * 4608) return;
    int o = idx / 4608;
    int k = idx - o * 4608;
    int tap = k >> 9, c = k & 511;
    float v = fw[o * 4608 + c * 9 + tap];
    __nv_bfloat16 h = __float2bfloat16(v);
    wh[idx] = h;
    wl[idx] = __float2bfloat16(v - __bfloat162float(h));
}

// ============================ tensor-core GEMM (mma.sync bf16 split) =========
// C[M,N] = epi(A[M,K] @ B[N,K]^T), A/B as bf16 (hi,lo) pairs; 3-product split.
// CTA tile 128 x NT (NT=128 or 256), BK=32, 3-stage cp.async pipeline.
// 8 warps, warp tile 64 x NT/4.
// EPI 0: alpha*(acc+bias[n]);  EPI 1: relu(acc*sc[n]+sh[n])
// CONV 1: A gathered implicitly from (B,32,32,512) with 3x3 pad-1 taps.

template<int EPI, int CONV, int NT>
__global__ void __launch_bounds__(256, 1)
tgemm_k(const __nv_bfloat16* __restrict__ Ah, const __nv_bfloat16* __restrict__ Al,
        const __nv_bfloat16* __restrict__ Bh, const __nv_bfloat16* __restrict__ Bl,
        const float* __restrict__ bias, const float* __restrict__ sc,
        const float* __restrict__ sh, float* __restrict__ C,
        int M, int N, int K, float alpha)
{
    constexpr int WN = NT / 4;          // warp n-tile: 32 or 64
    constexpr int NACC = WN / 8;        // 4 or 8
    constexpr int NHALF = WN / 32;      // 1 or 2
    constexpr int BOFF = 128 * 2 * 80;  // 20480: B tiles after A tiles
    constexpr int STAGE_B = (2 * 128 + 2 * NT) * 80;
    constexpr int ROWS_IT = (2 * 128 + 2 * NT) / 64;  // fill iters (8 or 12)

    extern __shared__ char smem[];
    const uint32_t sbase = smem_u32(smem);
    const int tid = threadIdx.x;
    const int wid = tid >> 5;
    const int lane = tid & 31;
    const int wm = wid >> 2;
    const int wn = wid & 3;
    const int bm = blockIdx.y << 7;
    const int bn = blockIdx.x * NT;

    const int nc = K >> 5;

    float acc[4][NACC][4];
#pragma unroll
    for (int i = 0; i < 4; i++)
#pragma unroll
        for (int j = 0; j < NACC; j++)
#pragma unroll
            for (int r = 0; r < 4; r++) acc[i][j][r] = 0.f;

    auto fill = [&](int stage, int k0) {
        uint32_t sb = sbase + stage * STAGE_B;
#pragma unroll
        for (int it = 0; it < ROWS_IT; it++) {
            int g = it * 256 + tid;
            int rr = g >> 2;
            int c4 = g & 3;
            if (rr < 256) {
                int t = rr >> 7;       // 0=Ah 1=Al
                int r = rr & 127;
                uint32_t dst = sb + t * 10240 + r * 80 + c4 * 16;
                if (!CONV) {
                    const __nv_bfloat16* src = (t ? Al : Ah) + (long)(bm + r) * K + k0 + c4 * 8;
                    cp16(dst, src, 1);
                } else {
                    int m = bm + r;
                    int cb = m >> 10, p = m & 1023, cy = p >> 5, cx = p & 31;
                    int tap = k0 >> 9;
                    int dy = tap / 3 - 1, dx = tap - (tap / 3) * 3 - 1;
                    int yy = cy + dy, xx = cx + dx;
                    int pred = ((unsigned)yy < 32u) && ((unsigned)xx < 32u);
                    long off = pred ? (((long)((cb * 32 + yy) * 32 + xx)) << 9) + (k0 & 511) + c4 * 8 : 0;
                    const __nv_bfloat16* src = (t ? Al : Ah) + off;
                    cp16(dst, src, pred);
                }
            } else {
                int rb = rr - 256;
                int t = rb / NT;
                int r = rb - t * NT;
                uint32_t dst = sb + BOFF + t * (NT * 80) + r * 80 + c4 * 16;
                const __nv_bfloat16* src = (t ? Bl : Bh) + (long)(bn + r) * K + k0 + c4 * 8;
                cp16(dst, src, 1);
            }
        }
    };

    for (int s = 0; s < 3; s++) {
        if (s < nc) fill(s, s << 5);
        asm volatile("cp.async.commit_group;" ::: "memory");
    }

    const int a_row = (lane & 15);
    const int a_kof = (lane >> 4) << 3;
    const int b_row = (lane & 7) + ((lane >> 4) << 3);
    const int b_kof = ((lane >> 3) & 1) << 3;

    for (int c = 0; c < nc; c++) {
        asm volatile("cp.async.wait_group 2;" ::: "memory");
        __syncthreads();
        uint32_t sb = sbase + (c % 3) * STAGE_B;
        uint32_t pAh = sb + (wm * 64 + a_row) * 80 + a_kof * 2;
        uint32_t pBh = sb + BOFF + (wn * WN + b_row) * 80 + b_kof * 2;

#pragma unroll
        for (int ks = 0; ks < 2; ks++) {
            uint32_t ah[4][4], al[4][4];
#pragma unroll
            for (int mi = 0; mi < 4; mi++) {
                ldmx4(ah[mi], pAh + mi * 16 * 80 + ks * 32);
                ldmx4(al[mi], pAh + 10240 + mi * 16 * 80 + ks * 32);
            }
#pragma unroll
            for (int nh = 0; nh < NHALF; nh++) {
                uint32_t bh[2][4], bl[2][4];
#pragma unroll
                for (int nj = 0; nj < 2; nj++) {
                    uint32_t pb = pBh + (nh * 32 + nj * 16) * 80 + ks * 32;
                    ldmx4(bh[nj], pb);
                    ldmx4(bl[nj], pb + NT * 80);
                }
#pragma unroll
                for (int mi = 0; mi < 4; mi++)
#pragma unroll
                    for (int n4 = 0; n4 < 4; n4++) {
                        const uint32_t* bhp = &bh[n4 >> 1][(n4 & 1) * 2];
                        const uint32_t* blp = &bl[n4 >> 1][(n4 & 1) * 2];
                        float* a = acc[mi][nh * 4 + n4];
                        hmma(a, ah[mi], bhp);
                        hmma(a, ah[mi], blp);
                        hmma(a, al[mi], bhp);
                    }
            }
        }
        __syncthreads();
        if (c + 3 < nc) fill(c % 3, (c + 3) << 5);
        asm volatile("cp.async.commit_group;" ::: "memory");
    }

    // epilogue
#pragma unroll
    for (int mi = 0; mi < 4; mi++) {
#pragma unroll
        for (int ni = 0; ni < NACC; ni++) {
            int row = bm + wm * 64 + mi * 16 + (lane >> 2);
            int col = bn + wn * WN + ni * 8 + (lane & 3) * 2;
            float2 e0, e1;
            if (EPI == 0) {
                float2 bv = *(const float2*)(bias + col);
                e0.x = alpha * (acc[mi][ni][0] + bv.x);
                e0.y = alpha * (acc[mi][ni][1] + bv.y);
                e1.x = alpha * (acc[mi][ni][2] + bv.x);
                e1.y = alpha * (acc[mi][ni][3] + bv.y);
            } else {
                float2 sv = *(const float2*)(sc + col);
                float2 hv = *(const float2*)(sh + col);
                e0.x = fmaxf(acc[mi][ni][0] * sv.x + hv.x, 0.f);
                e0.y = fmaxf(acc[mi][ni][1] * sv.y + hv.y, 0.f);
                e1.x = fmaxf(acc[mi][ni][2] * sv.x + hv.x, 0.f);
                e1.y = fmaxf(acc[mi][ni][3] * sv.y + hv.y, 0.f);
            }
            *(float2*)(C + (long)row * N + col) = e0;
            *(float2*)(C + (long)(row + 8) * N + col) = e1;
        }
    }
}

// ---------------- Haar DWT ----------------------------------------------------
__global__ void dwt_k(const float* __restrict__ xr, __nv_bfloat16* __restrict__ oh,
                      __nv_bfloat16* __restrict__ ol)
{
    int idx = blockIdx.x * 256 + threadIdx.x;
    int cq = idx & 31;
    int pos = idx >> 5;
    int b = pos >> 10;
    int r = pos & 1023;
    int h = r >> 5, w = r & 31;
    const float* base = xr + ((long)((b * 64 + 2 * h) * 64 + 2 * w)) * 128 + cq * 4;
    float4 x00 = *(const float4*)(base);
    float4 x01 = *(const float4*)(base + 128);
    float4 x10 = *(const float4*)(base + 64 * 128);
    float4 x11 = *(const float4*)(base + 64 * 128 + 128);
    float4 ll, lh, hl, hh;
#define DWT1(f) \
    ll.f = 0.5f * (x00.f + x01.f + x10.f + x11.f); \
    lh.f = 0.5f * (x00.f + x01.f - x10.f - x11.f); \
    hl.f = 0.5f * (x00.f - x01.f + x10.f - x11.f); \
    hh.f = 0.5f * (x00.f - x01.f - x10.f + x11.f);
    DWT1(x) DWT1(y) DWT1(z) DWT1(w)
#undef DWT1
    long o = (long)pos * 512 + cq * 4;
    store_pair4(oh + o,       ol + o,       ll);
    store_pair4(oh + o + 128, ol + o + 128, lh);
    store_pair4(oh + o + 256, ol + o + 256, hl);
    store_pair4(oh + o + 384, ol + o + 384, hh);
}

// ---------------- Haar IDWT ----------------------------------------------------
__global__ void idwt_k(const float* __restrict__ d2, __nv_bfloat16* __restrict__ aph,
                       __nv_bfloat16* __restrict__ apl)
{
    int idx = blockIdx.x * 256 + threadIdx.x;
    int cq = idx & 31;
    int pos = idx >> 5;
    int b = pos >> 10;
    int r = pos & 1023;
    int h = r >> 5, w = r & 31;
    const float* ip = d2 + (long)pos * 512 + cq * 4;
    float4 ll = *(const float4*)(ip);
    float4 lh = *(const float4*)(ip + 128);
    float4 hl = *(const float4*)(ip + 256);
    float4 hh = *(const float4*)(ip + 384);
    float4 y00, y01, y10, y11;
#define IDWT1(f) \
    y00.f = 0.5f * (ll.f + lh.f + hl.f + hh.f); \
    y01.f = 0.5f * (ll.f + lh.f - hl.f - hh.f); \
    y10.f = 0.5f * (ll.f - lh.f + hl.f - hh.f); \
    y11.f = 0.5f * (ll.f - lh.f - hl.f + hh.f);
    IDWT1(x) IDWT1(y) IDWT1(z) IDWT1(w)
#undef IDWT1
    long base = ((long)(b * 4096 + (2 * h) * 64 + 2 * w)) * 640 + 512 + cq * 4;
    store_pair4(aph + base,                apl + base,                y00);
    store_pair4(aph + base + 640,          apl + base + 640,          y01);
    store_pair4(aph + base + 64 * 640,       apl + base + 64 * 640,       y10);
    store_pair4(aph + base + 64 * 640 + 640, apl + base + 64 * 640 + 640, y11);
}

// ---------------- im2col for kvq conv ----------------------------------------
__global__ void im2col_k(const float* __restrict__ d2, __nv_bfloat16* __restrict__ ch,
                         __nv_bfloat16* __restrict__ cl)
{
    int idx = blockIdx.x * 256 + threadIdx.x;
    if (idx >= 1024 * 2048) return;
    int t = idx >> 11;
    int k4 = (idx & 2047) * 4;
    int c = k4 >> 4;
    int ij = k4 & 15;
    int i = ij >> 2;
    int b = t >> 6;
    int pp = t & 63;
    int ph = pp >> 3, pw = pp & 7;
    int y = 4 * ph + i;
    int x0 = 4 * pw;
    const float* sp = d2 + ((long)((b * 32 + y) * 32 + x0)) * 512 + c;
    float4 v;
    v.x = sp[0]; v.y = sp[512]; v.z = sp[1024]; v.w = sp[1536];
    store_pair4(ch + (long)t * 8192 + k4, cl + (long)t * 8192 + k4, v);
}

// ---------------- layernorm -> bf16 pairs ------------------------------------
__global__ void ln_k(const float* __restrict__ in, const float* __restrict__ g,
                     const float* __restrict__ be, __nv_bfloat16* __restrict__ oh,
                     __nv_bfloat16* __restrict__ ol)
{
    int row = blockIdx.x;
    const float* p = in + (long)row * 512;
    int tid = threadIdx.x;
    float x0 = p[tid], x1 = p[tid + 256];
    float s = x0 + x1, q = x0 * x0 + x1 * x1;
    __shared__ float red[16];
    __shared__ float mv[2];
#pragma unroll
    for (int o = 16; o; o >>= 1) {
        s += __shfl_down_sync(0xffffffffu, s, o);
        q += __shfl_down_sync(0xffffffffu, q, o);
    }
    if ((tid & 31) == 0) { red[tid >> 5] = s; red[8 + (tid >> 5)] = q; }
    __syncthreads();
    if (tid == 0) {
        float S = 0.f, Q = 0.f;
        for (int i = 0; i < 8; i++) { S += red[i]; Q += red[8 + i]; }
        float mean = S * (1.f / 512.f);
        float var = Q * (1.f / 512.f) - mean * mean;
        mv[0] = mean;
        mv[1] = rsqrtf(var + 1e-5f);
    }
    __syncthreads();
    float mean = mv[0], inv = mv[1];
    float v0 = (x0 - mean) * inv * g[tid] + be[tid];
    float v1 = (x1 - mean) * inv * g[tid + 256] + be[tid + 256];
    __nv_bfloat16 h0 = __float2bfloat16(v0), h1 = __float2bfloat16(v1);
    oh[(long)row * 512 + tid] = h0;
    oh[(long)row * 512 + tid + 256] = h1;
    ol[(long)row * 512 + tid] = __float2bfloat16(v0 - __bfloat162float(h0));
    ol[(long)row * 512 + tid + 256] = __float2bfloat16(v1 - __bfloat162float(h1));
}

// ---------------- attention: Lk=64 -------------------------------------------
__global__ void __launch_bounds__(128)
attn_k(const float* __restrict__ qbuf, const float* __restrict__ kv,
       float* __restrict__ attn_out, __nv_bfloat16* __restrict__ aph,
       __nv_bfloat16* __restrict__ apl)
{
    __shared__ float ks[64][65];
    __shared__ float vs[64][65];
    int b = blockIdx.x >> 3;
    int h = blockIdx.x & 7;
    int tid = threadIdx.x;
    for (int i = tid; i < 64 * 64; i += 128) {
        int t = i >> 6, d = i & 63;
        const float* kr = kv + (long)(b * 64 + t) * 1024 + h * 64;
        ks[t][d] = kr[d];
        vs[t][d] = kr[512 + d];
    }
    __syncthreads();
    int l = blockIdx.y * 128 + tid;
    long m = (long)b * 4096 + l;
    const float* qp = qbuf + m * 512 + h * 64;
    float qr[64];
#pragma unroll
    for (int d = 0; d < 64; d++) qr[d] = qp[d];
    float s[64];
    float mx = -1e30f;
#pragma unroll
    for (int j = 0; j < 64; j++) {
        float a = 0.f;
#pragma unroll
        for (int d = 0; d < 64; d++) a = fmaf(qr[d], ks[j][d], a);
        s[j] = a;
        mx = fmaxf(mx, a);
    }
    float sum = 0.f;
#pragma unroll
    for (int j = 0; j < 64; j++) { s[j] = __expf(s[j] - mx); sum += s[j]; }
    float inv = 1.f / sum;
    float* ao = attn_out + (((long)(b * 8 + h) * 4096 + l) << 6);
#pragma unroll
    for (int j = 0; j < 64; j++) { s[j] *= inv; ao[j] = s[j]; }
    __nv_bfloat16* poh = aph + m * 640 + h * 64;
    __nv_bfloat16* pol = apl + m * 640 + h * 64;
#pragma unroll
    for (int d = 0; d < 64; d += 2) {
        float a0 = 0.f, a1 = 0.f;
#pragma unroll
        for (int j = 0; j < 64; j++) {
            a0 = fmaf(s[j], vs[j][d], a0);
            a1 = fmaf(s[j], vs[j][d + 1], a1);
        }
        __nv_bfloat16 h0 = __float2bfloat16(a0), h1 = __float2bfloat16(a1);
        *(__nv_bfloat162*)(poh + d) = __halves2bfloat162(h0, h1);
        __nv_bfloat16 l0 = __float2bfloat16(a0 - __bfloat162float(h0));
        __nv_bfloat16 l1 = __float2bfloat16(a1 - __bfloat162float(h1));
        *(__nv_bfloat162*)(pol + d) = __halves2bfloat162(l0, l1);
    }
}

// ============================ launch =========================================
static void* symaddr_(const void* sym)
{
    void* p = nullptr;
    cudaGetSymbolAddress(&p, sym);
    return p;
}
#define SYM(T, name) T* name = (T*)symaddr_(g_##name)

#define SMEM128 ((2 * 128 + 2 * 128) * 80 * 3)   // 122880
#define SMEM256 ((2 * 128 + 2 * 256) * 80 * 3)   // 184320

extern "C" void kernel_launch(void* const* d_in, const int* in_sizes, int n_in,
                              void* d_out, int out_size)
{
    const float* x      = (const float*)d_in[0];
    const float* red_w  = (const float*)d_in[1];
    const float* red_b  = (const float*)d_in[2];
    const float* bn1_g  = (const float*)d_in[3];
    const float* bn1_b  = (const float*)d_in[4];
    const float* bn1_m  = (const float*)d_in[5];
    const float* bn1_v  = (const float*)d_in[6];
    const float* filt_w = (const float*)d_in[7];
    const float* filt_b = (const float*)d_in[8];
    const float* bn2_g  = (const float*)d_in[9];
    const float* bn2_b  = (const float*)d_in[10];
    const float* bn2_m  = (const float*)d_in[11];
    const float* bn2_v  = (const float*)d_in[12];
    const float* kvq_w  = (const float*)d_in[13];
    const float* kvq_b  = (const float*)d_in[14];
    const float* q_w    = (const float*)d_in[15];
    const float* q_b    = (const float*)d_in[16];
    const float* ln_g   = (const float*)d_in[17];
    const float* ln_b   = (const float*)d_in[18];
    const float* kv_w   = (const float*)d_in[19];
    const float* kv_b   = (const float*)d_in[20];
    const float* proj_w = (const float*)d_in[21];
    const float* proj_b = (const float*)d_in[22];

    float* out  = (float*)d_out;
    float* attn = out + OUT_ELEMS;

    SYM(float, q); SYM(float, xred); SYM(float, dwt2); SYM(float, kvtok); SYM(float, kv);
    SYM(float, sc1); SYM(float, sh1); SYM(float, sc2); SYM(float, sh2);
    SYM(__nv_bfloat16, xh);  SYM(__nv_bfloat16, xl);
    SYM(__nv_bfloat16, d1h); SYM(__nv_bfloat16, d1l);
    SYM(__nv_bfloat16, aph); SYM(__nv_bfloat16, apl);
    SYM(__nv_bfloat16, lnh); SYM(__nv_bfloat16, lnl);
    SYM(__nv_bfloat16, imh); SYM(__nv_bfloat16, iml);
    SYM(__nv_bfloat16, qwh); SYM(__nv_bfloat16, qwl);
    SYM(__nv_bfloat16, rwh); SYM(__nv_bfloat16, rwl);
    SYM(__nv_bfloat16, cwh); SYM(__nv_bfloat16, cwl);
    SYM(__nv_bfloat16, kqwh); SYM(__nv_bfloat16, kqwl);
    SYM(__nv_bfloat16, kvwh); SYM(__nv_bfloat16, kvwl);
    SYM(__nv_bfloat16, pwh); SYM(__nv_bfloat16, pwl);

    cudaFuncSetAttribute(tgemm_k<0, 0, 256>, cudaFuncAttributeMaxDynamicSharedMemorySize, SMEM256);
    cudaFuncSetAttribute(tgemm_k<1, 1, 256>, cudaFuncAttributeMaxDynamicSharedMemorySize, SMEM256);
    cudaFuncSetAttribute(tgemm_k<0, 0, 128>, cudaFuncAttributeMaxDynamicSharedMemorySize, SMEM128);
    cudaFuncSetAttribute(tgemm_k<1, 0, 128>, cudaFuncAttributeMaxDynamicSharedMemorySize, SMEM128);

    // ---- prep ----
    bnprep_k<<<1, 128>>>(bn1_g, bn1_b, bn1_m, bn1_v, red_b, sc1, sh1, 128);
    bnprep_k<<<2, 256>>>(bn2_g, bn2_b, bn2_m, bn2_v, filt_b, sc2, sh2, 512);
    cvt_k<<<32768, 256>>>(x, xh, xl, 33554432);
    cvt_k<<<256, 256>>>(q_w, qwh, qwl, 262144);
    cvt_k<<<64, 256>>>(red_w, rwh, rwl, 65536);
    cvt_k<<<4096, 256>>>(kvq_w, kqwh, kqwl, 4194304);
    cvt_k<<<512, 256>>>(kv_w, kvwh, kvwl, 524288);
    cvt_k<<<320, 256>>>(proj_w, pwh, pwl, 327680);
    wremap_k<<<9216, 256>>>(filt_w, cwh, cwl);

    // ---- q = (x @ q_w^T + q_b) * 0.125 ----
    tgemm_k<0, 0, 256><<<dim3(2, 512), 256, SMEM256>>>(xh, xl, qwh, qwl, q_b, nullptr, nullptr,
                                                       q, 65536, 512, 512, 0.125f);
    // ---- xred = relu(bn1(x @ red_w^T)) ----
    tgemm_k<1, 0, 128><<<dim3(1, 512), 256, SMEM128>>>(xh, xl, rwh, rwl, nullptr, sc1, sh1,
                                                       xred, 65536, 128, 512, 1.f);
    // ---- DWT -> bf16 pairs ----
    dwt_k<<<2048, 256>>>(xred, d1h, d1l);
    // ---- conv3x3 + bn2 + relu (implicit im2col) ----
    tgemm_k<1, 1, 256><<<dim3(2, 128), 256, SMEM256>>>(d1h, d1l, cwh, cwl, nullptr, sc2, sh2,
                                                       dwt2, 16384, 512, 4608, 1.f);
    // ---- IDWT -> aproj pairs cols [512,640) ----
    idwt_k<<<2048, 256>>>(dwt2, aph, apl);
    // ---- kvq conv via im2col ----
    im2col_k<<<8192, 256>>>(dwt2, imh, iml);
    tgemm_k<0, 0, 128><<<dim3(4, 8), 256, SMEM128>>>(imh, iml, kqwh, kqwl, kvq_b, nullptr, nullptr,
                                                     kvtok, 1024, 512, 8192, 1.f);
    // ---- layernorm + kv GEMM ----
    ln_k<<<1024, 256>>>(kvtok, ln_g, ln_b, lnh, lnl);
    tgemm_k<0, 0, 128><<<dim3(8, 8), 256, SMEM128>>>(lnh, lnl, kvwh, kvwl, kv_b, nullptr, nullptr,
                                                     kv, 1024, 1024, 512, 1.f);
    // ---- attention: attn output + aproj pairs cols [0,512) ----
    attn_k<<<dim3(128, 32), 128>>>(q, kv, attn, aph, apl);
    // ---- proj ----
    tgemm_k<0, 0, 256><<<dim3(2, 512), 256, SMEM256>>>(aph, apl, pwh, pwl, proj_b, nullptr, nullptr,
                                                       out, 65536, 512, 640, 1.f);
}

// round 5
// speedup vs baseline: 2.2304x; 1.0216x over previous
#include <cuda_runtime.h>
#include <cuda_bf16.h>
#include <cstdint>
#include <math.h>

// ============================ PTX helpers (sm_80+ path) =====================
__device__ __forceinline__ uint32_t smem_u32(const void* p) {
    uint32_t a;
    asm("{ .reg .u64 t; cvta.to.shared.u64 t, %1; cvt.u32.u64 %0, t; }" : "=r"(a) : "l"(p));
    return a;
}
__device__ __forceinline__ void cp16(uint32_t dst, const void* src, int pred) {
    asm volatile("cp.async.cg.shared.global [%0], [%1], 16, %2;"
                 :: "r"(dst), "l"(src), "r"(pred ? 16 : 0) : "memory");
}
__device__ __forceinline__ void ldmx4(uint32_t* r, uint32_t addr) {
    asm volatile("ldmatrix.sync.aligned.m8n8.x4.shared.b16 {%0,%1,%2,%3}, [%4];"
                 : "=r"(r[0]), "=r"(r[1]), "=r"(r[2]), "=r"(r[3]) : "r"(addr));
}
__device__ __forceinline__ void hmma(float* d, const uint32_t* a, const uint32_t* b) {
    asm volatile("mma.sync.aligned.m16n8k16.row.col.f32.bf16.bf16.f32 "
                 "{%0,%1,%2,%3}, {%4,%5,%6,%7}, {%8,%9}, {%0,%1,%2,%3};"
                 : "+f"(d[0]), "+f"(d[1]), "+f"(d[2]), "+f"(d[3])
                 : "r"(a[0]), "r"(a[1]), "r"(a[2]), "r"(a[3]), "r"(b[0]), "r"(b[1]));
}

// ============================ scratch ============================
#define OUT_ELEMS 33554432
static __device__ float g_q[33554432];
static __device__ float g_xred[8388608];
static __device__ float g_dwt2[8388608];
static __device__ float g_kvtok[524288];
static __device__ float g_kv[1048576];
static __device__ float g_sc1[128], g_sh1[128], g_sc2[512], g_sh2[512];

static __device__ __nv_bfloat16 g_xh[33554432], g_xl[33554432];
static __device__ __nv_bfloat16 g_d1h[8388608],  g_d1l[8388608];
static __device__ __nv_bfloat16 g_aph[41943040], g_apl[41943040];
static __device__ __nv_bfloat16 g_lnh[524288],   g_lnl[524288];
static __device__ __nv_bfloat16 g_imh[8388608],  g_iml[8388608];
static __device__ __nv_bfloat16 g_qwh[262144],   g_qwl[262144];
static __device__ __nv_bfloat16 g_rwh[65536],    g_rwl[65536];
static __device__ __nv_bfloat16 g_cwh[2359296],  g_cwl[2359296];
static __device__ __nv_bfloat16 g_kqwh[4194304], g_kqwl[4194304];
static __device__ __nv_bfloat16 g_kvwh[524288],  g_kvwl[524288];
static __device__ __nv_bfloat16 g_pwh[327680],   g_pwl[327680];

// ============================ small helpers ============================
__device__ __forceinline__ void store_pair4(__nv_bfloat16* ph, __nv_bfloat16* pl, float4 v)
{
    __nv_bfloat16 hx = __float2bfloat16(v.x), hy = __float2bfloat16(v.y);
    __nv_bfloat16 hz = __float2bfloat16(v.z), hw = __float2bfloat16(v.w);
    ((__nv_bfloat162*)ph)[0] = __halves2bfloat162(hx, hy);
    ((__nv_bfloat162*)ph)[1] = __halves2bfloat162(hz, hw);
    __nv_bfloat16 lx = __float2bfloat16(v.x - __bfloat162float(hx));
    __nv_bfloat16 ly = __float2bfloat16(v.y - __bfloat162float(hy));
    __nv_bfloat16 lz = __float2bfloat16(v.z - __bfloat162float(hz));
    __nv_bfloat16 lw = __float2bfloat16(v.w - __bfloat162float(hw));
    ((__nv_bfloat162*)pl)[0] = __halves2bfloat162(lx, ly);
    ((__nv_bfloat162*)pl)[1] = __halves2bfloat162(lz, lw);
}

__global__ void cvt_k(const float* __restrict__ in, __nv_bfloat16* __restrict__ h,
                      __nv_bfloat16* __restrict__ l, int n)
{
    int i = (blockIdx.x * 256 + threadIdx.x) * 4;
    if (i >= n) return;
    store_pair4(h + i, l + i, *(const float4*)(in + i));
}

__global__ void bnprep_k(const float* __restrict__ g, const float* __restrict__ be,
                         const float* __restrict__ mu, const float* __restrict__ va,
                         const float* __restrict__ bias, float* __restrict__ sc,
                         float* __restrict__ sh, int n)
{
    int i = blockIdx.x * blockDim.x + threadIdx.x;
    if (i < n) {
        float s = g[i] * rsqrtf(va[i] + 1e-5f);
        sc[i] = s;
        sh[i] = be[i] - mu[i] * s + bias[i] * s;
    }
}

// filt_w (o,c,3,3) -> (o, tap*512+c), split into bf16 pairs
__global__ void wremap_k(const float* __restrict__ fw, __nv_bfloat16* __restrict__ wh,
                         __nv_bfloat16* __restrict__ wl)
{
    int idx = blockIdx.x * 256 + threadIdx.x;
    if (idx >= 512 * 4608) return;
    int o = idx / 4608;
    int k = idx - o * 4608;
    int tap = k >> 9, c = k & 511;
    float v = fw[o * 4608 + c * 9 + tap];
    __nv_bfloat16 h = __float2bfloat16(v);
    wh[idx] = h;
    wl[idx] = __float2bfloat16(v - __bfloat162float(h));
}

// ============================ tensor-core GEMM (mma.sync bf16 split) =========
// C[M,N] = epi(A[M,K] @ B[N,K]^T), A/B as bf16 (hi,lo) pairs; 3-product split.
// CTA tile 128x128, BK=32, 2-stage cp.async pipeline, 2 CTAs/SM (16 warps).
// 8 warps, warp tile 64x32.
// EPI 0: alpha*(acc+bias[n]);  EPI 1: relu(acc*sc[n]+sh[n])
// CONV 1: A gathered implicitly from (B,32,32,512) with 3x3 pad-1 taps.
#define TILE_B 10240            // 128 rows * 80 bytes
#define STAGE_B (4 * TILE_B)    // Ah, Al, Bh, Bl = 40960
#define SMEM_DYN (2 * STAGE_B)  // 81920 -> 2 CTAs/SM

template<int EPI, int CONV>
__global__ void __launch_bounds__(256, 2)
tgemm_k(const __nv_bfloat16* __restrict__ Ah, const __nv_bfloat16* __restrict__ Al,
        const __nv_bfloat16* __restrict__ Bh, const __nv_bfloat16* __restrict__ Bl,
        const float* __restrict__ bias, const float* __restrict__ sc,
        const float* __restrict__ sh, float* __restrict__ C,
        int M, int N, int K, float alpha)
{
    extern __shared__ char smem[];
    const uint32_t sbase = smem_u32(smem);
    const int tid = threadIdx.x;
    const int wid = tid >> 5;
    const int lane = tid & 31;
    const int wm = wid >> 2;
    const int wn = wid & 3;
    const int bm = blockIdx.y << 7;
    const int bn = blockIdx.x << 7;

    const int nc = K >> 5;

    float acc[4][4][4];
#pragma unroll
    for (int i = 0; i < 4; i++)
#pragma unroll
        for (int j = 0; j < 4; j++)
#pragma unroll
            for (int r = 0; r < 4; r++) acc[i][j][r] = 0.f;

    auto fill = [&](int stage, int k0) {
        uint32_t sb = sbase + stage * STAGE_B;
#pragma unroll
        for (int it = 0; it < 8; it++) {
            int g = it * 256 + tid;
            int t = g >> 9;           // 0=Ah 1=Al 2=Bh 3=Bl
            int s = g & 511;
            int r = s >> 2;
            int c4 = s & 3;
            uint32_t dst = sb + t * TILE_B + r * 80 + c4 * 16;
            if (t >= 2) {
                const __nv_bfloat16* src = (t == 2 ? Bh : Bl) + (long)(bn + r) * K + k0 + c4 * 8;
                cp16(dst, src, 1);
            } else if (!CONV) {
                const __nv_bfloat16* src = (t == 0 ? Ah : Al) + (long)(bm + r) * K + k0 + c4 * 8;
                cp16(dst, src, 1);
            } else {
                int m = bm + r;
                int cb = m >> 10, p = m & 1023, cy = p >> 5, cx = p & 31;
                int tap = k0 >> 9;
                int dy = tap / 3 - 1, dx = tap - (tap / 3) * 3 - 1;
                int yy = cy + dy, xx = cx + dx;
                int pred = ((unsigned)yy < 32u) && ((unsigned)xx < 32u);
                long off = pred ? (((long)((cb * 32 + yy) * 32 + xx)) << 9) + (k0 & 511) + c4 * 8 : 0;
                const __nv_bfloat16* src = (t == 0 ? Ah : Al) + off;
                cp16(dst, src, pred);
            }
        }
    };

    // prologue: 2 stages
    fill(0, 0);
    asm volatile("cp.async.commit_group;" ::: "memory");
    if (nc > 1) fill(1, 32);
    asm volatile("cp.async.commit_group;" ::: "memory");

    const int a_row = (lane & 15);
    const int a_kof = (lane >> 4) << 3;
    const int b_row = (lane & 7) + ((lane >> 4) << 3);
    const int b_kof = ((lane >> 3) & 1) << 3;

    for (int c = 0; c < nc; c++) {
        asm volatile("cp.async.wait_group 1;" ::: "memory");
        __syncthreads();
        uint32_t sb = sbase + (c & 1) * STAGE_B;
        uint32_t pAh = sb + (wm * 64 + a_row) * 80 + a_kof * 2;
        uint32_t pAl = pAh + TILE_B;
        uint32_t pBh = sb + 2 * TILE_B + (wn * 32 + b_row) * 80 + b_kof * 2;
        uint32_t pBl = pBh + TILE_B;

#pragma unroll
        for (int ks = 0; ks < 2; ks++) {
            uint32_t ah[4][4], al[4][4], bh[2][4], bl[2][4];
#pragma unroll
            for (int mi = 0; mi < 4; mi++) {
                ldmx4(ah[mi], pAh + mi * 16 * 80 + ks * 32);
                ldmx4(al[mi], pAl + mi * 16 * 80 + ks * 32);
            }
#pragma unroll
            for (int nj = 0; nj < 2; nj++) {
                ldmx4(bh[nj], pBh + nj * 16 * 80 + ks * 32);
                ldmx4(bl[nj], pBl + nj * 16 * 80 + ks * 32);
            }
#pragma unroll
            for (int mi = 0; mi < 4; mi++)
#pragma unroll
                for (int ni = 0; ni < 4; ni++) {
                    const uint32_t* bhp = &bh[ni >> 1][(ni & 1) * 2];
                    const uint32_t* blp = &bl[ni >> 1][(ni & 1) * 2];
                    hmma(acc[mi][ni], ah[mi], bhp);
                    hmma(acc[mi][ni], ah[mi], blp);
                    hmma(acc[mi][ni], al[mi], bhp);
                }
        }
        __syncthreads();
        if (c + 2 < nc) fill(c & 1, (c + 2) << 5);
        asm volatile("cp.async.commit_group;" ::: "memory");
    }

    // epilogue
#pragma unroll
    for (int mi = 0; mi < 4; mi++) {
#pragma unroll
        for (int ni = 0; ni < 4; ni++) {
            int row = bm + wm * 64 + mi * 16 + (lane >> 2);
            int col = bn + wn * 32 + ni * 8 + (lane & 3) * 2;
            float2 e0, e1;
            if (EPI == 0) {
                float2 bv = *(const float2*)(bias + col);
                e0.x = alpha * (acc[mi][ni][0] + bv.x);
                e0.y = alpha * (acc[mi][ni][1] + bv.y);
                e1.x = alpha * (acc[mi][ni][2] + bv.x);
                e1.y = alpha * (acc[mi][ni][3] + bv.y);
            } else {
                float2 sv = *(const float2*)(sc + col);
                float2 hv = *(const float2*)(sh + col);
                e0.x = fmaxf(acc[mi][ni][0] * sv.x + hv.x, 0.f);
                e0.y = fmaxf(acc[mi][ni][1] * sv.y + hv.y, 0.f);
                e1.x = fmaxf(acc[mi][ni][2] * sv.x + hv.x, 0.f);
                e1.y = fmaxf(acc[mi][ni][3] * sv.y + hv.y, 0.f);
            }
            *(float2*)(C + (long)row * N + col) = e0;
            *(float2*)(C + (long)(row + 8) * N + col) = e1;
        }
    }
}

// ---------------- Haar DWT ----------------------------------------------------
__global__ void dwt_k(const float* __restrict__ xr, __nv_bfloat16* __restrict__ oh,
                      __nv_bfloat16* __restrict__ ol)
{
    int idx = blockIdx.x * 256 + threadIdx.x;
    int cq = idx & 31;
    int pos = idx >> 5;
    int b = pos >> 10;
    int r = pos & 1023;
    int h = r >> 5, w = r & 31;
    const float* base = xr + ((long)((b * 64 + 2 * h) * 64 + 2 * w)) * 128 + cq * 4;
    float4 x00 = *(const float4*)(base);
    float4 x01 = *(const float4*)(base + 128);
    float4 x10 = *(const float4*)(base + 64 * 128);
    float4 x11 = *(const float4*)(base + 64 * 128 + 128);
    float4 ll, lh, hl, hh;
#define DWT1(f) \
    ll.f = 0.5f * (x00.f + x01.f + x10.f + x11.f); \
    lh.f = 0.5f * (x00.f + x01.f - x10.f - x11.f); \
    hl.f = 0.5f * (x00.f - x01.f + x10.f - x11.f); \
    hh.f = 0.5f * (x00.f - x01.f - x10.f + x11.f);
    DWT1(x) DWT1(y) DWT1(z) DWT1(w)
#undef DWT1
    long o = (long)pos * 512 + cq * 4;
    store_pair4(oh + o,       ol + o,       ll);
    store_pair4(oh + o + 128, ol + o + 128, lh);
    store_pair4(oh + o + 256, ol + o + 256, hl);
    store_pair4(oh + o + 384, ol + o + 384, hh);
}

// ---------------- Haar IDWT ----------------------------------------------------
__global__ void idwt_k(const float* __restrict__ d2, __nv_bfloat16* __restrict__ aph,
                       __nv_bfloat16* __restrict__ apl)
{
    int idx = blockIdx.x * 256 + threadIdx.x;
    int cq = idx & 31;
    int pos = idx >> 5;
    int b = pos >> 10;
    int r = pos & 1023;
    int h = r >> 5, w = r & 31;
    const float* ip = d2 + (long)pos * 512 + cq * 4;
    float4 ll = *(const float4*)(ip);
    float4 lh = *(const float4*)(ip + 128);
    float4 hl = *(const float4*)(ip + 256);
    float4 hh = *(const float4*)(ip + 384);
    float4 y00, y01, y10, y11;
#define IDWT1(f) \
    y00.f = 0.5f * (ll.f + lh.f + hl.f + hh.f); \
    y01.f = 0.5f * (ll.f + lh.f - hl.f - hh.f); \
    y10.f = 0.5f * (ll.f - lh.f + hl.f - hh.f); \
    y11.f = 0.5f * (ll.f - lh.f - hl.f + hh.f);
    IDWT1(x) IDWT1(y) IDWT1(z) IDWT1(w)
#undef IDWT1
    long base = ((long)(b * 4096 + (2 * h) * 64 + 2 * w)) * 640 + 512 + cq * 4;
    store_pair4(aph + base,                apl + base,                y00);
    store_pair4(aph + base + 640,          apl + base + 640,          y01);
    store_pair4(aph + base + 64 * 640,       apl + base + 64 * 640,       y10);
    store_pair4(aph + base + 64 * 640 + 640, apl + base + 64 * 640 + 640, y11);
}

// ---------------- im2col for kvq conv ----------------------------------------
__global__ void im2col_k(const float* __restrict__ d2, __nv_bfloat16* __restrict__ ch,
                         __nv_bfloat16* __restrict__ cl)
{
    int idx = blockIdx.x * 256 + threadIdx.x;
    if (idx >= 1024 * 2048) return;
    int t = idx >> 11;
    int k4 = (idx & 2047) * 4;
    int c = k4 >> 4;
    int ij = k4 & 15;
    int i = ij >> 2;
    int b = t >> 6;
    int pp = t & 63;
    int ph = pp >> 3, pw = pp & 7;
    int y = 4 * ph + i;
    int x0 = 4 * pw;
    const float* sp = d2 + ((long)((b * 32 + y) * 32 + x0)) * 512 + c;
    float4 v;
    v.x = sp[0]; v.y = sp[512]; v.z = sp[1024]; v.w = sp[1536];
    store_pair4(ch + (long)t * 8192 + k4, cl + (long)t * 8192 + k4, v);
}

// ---------------- layernorm -> bf16 pairs ------------------------------------
__global__ void ln_k(const float* __restrict__ in, const float* __restrict__ g,
                     const float* __restrict__ be, __nv_bfloat16* __restrict__ oh,
                     __nv_bfloat16* __restrict__ ol)
{
    int row = blockIdx.x;
    const float* p = in + (long)row * 512;
    int tid = threadIdx.x;
    float x0 = p[tid], x1 = p[tid + 256];
    float s = x0 + x1, q = x0 * x0 + x1 * x1;
    __shared__ float red[16];
    __shared__ float mv[2];
#pragma unroll
    for (int o = 16; o; o >>= 1) {
        s += __shfl_down_sync(0xffffffffu, s, o);
        q += __shfl_down_sync(0xffffffffu, q, o);
    }
    if ((tid & 31) == 0) { red[tid >> 5] = s; red[8 + (tid >> 5)] = q; }
    __syncthreads();
    if (tid == 0) {
        float S = 0.f, Q = 0.f;
        for (int i = 0; i < 8; i++) { S += red[i]; Q += red[8 + i]; }
        float mean = S * (1.f / 512.f);
        float var = Q * (1.f / 512.f) - mean * mean;
        mv[0] = mean;
        mv[1] = rsqrtf(var + 1e-5f);
    }
    __syncthreads();
    float mean = mv[0], inv = mv[1];
    float v0 = (x0 - mean) * inv * g[tid] + be[tid];
    float v1 = (x1 - mean) * inv * g[tid + 256] + be[tid + 256];
    __nv_bfloat16 h0 = __float2bfloat16(v0), h1 = __float2bfloat16(v1);
    oh[(long)row * 512 + tid] = h0;
    oh[(long)row * 512 + tid + 256] = h1;
    ol[(long)row * 512 + tid] = __float2bfloat16(v0 - __bfloat162float(h0));
    ol[(long)row * 512 + tid + 256] = __float2bfloat16(v1 - __bfloat162float(h1));
}

// ---------------- attention: Lk=64 -------------------------------------------
__global__ void __launch_bounds__(128)
attn_k(const float* __restrict__ qbuf, const float* __restrict__ kv,
       float* __restrict__ attn_out, __nv_bfloat16* __restrict__ aph,
       __nv_bfloat16* __restrict__ apl)
{
    __shared__ float ks[64][65];
    __shared__ float vs[64][65];
    int b = blockIdx.x >> 3;
    int h = blockIdx.x & 7;
    int tid = threadIdx.x;
    for (int i = tid; i < 64 * 64; i += 128) {
        int t = i >> 6, d = i & 63;
        const float* kr = kv + (long)(b * 64 + t) * 1024 + h * 64;
        ks[t][d] = kr[d];
        vs[t][d] = kr[512 + d];
    }
    __syncthreads();
    int l = blockIdx.y * 128 + tid;
    long m = (long)b * 4096 + l;
    const float* qp = qbuf + m * 512 + h * 64;
    float qr[64];
#pragma unroll
    for (int d = 0; d < 64; d++) qr[d] = qp[d];
    float s[64];
    float mx = -1e30f;
#pragma unroll
    for (int j = 0; j < 64; j++) {
        float a = 0.f;
#pragma unroll
        for (int d = 0; d < 64; d++) a = fmaf(qr[d], ks[j][d], a);
        s[j] = a;
        mx = fmaxf(mx, a);
    }
    float sum = 0.f;
#pragma unroll
    for (int j = 0; j < 64; j++) { s[j] = __expf(s[j] - mx); sum += s[j]; }
    float inv = 1.f / sum;
    float* ao = attn_out + (((long)(b * 8 + h) * 4096 + l) << 6);
#pragma unroll
    for (int j = 0; j < 64; j++) { s[j] *= inv; ao[j] = s[j]; }
    __nv_bfloat16* poh = aph + m * 640 + h * 64;
    __nv_bfloat16* pol = apl + m * 640 + h * 64;
#pragma unroll
    for (int d = 0; d < 64; d += 2) {
        float a0 = 0.f, a1 = 0.f;
#pragma unroll
        for (int j = 0; j < 64; j++) {
            a0 = fmaf(s[j], vs[j][d], a0);
            a1 = fmaf(s[j], vs[j][d + 1], a1);
        }
        __nv_bfloat16 h0 = __float2bfloat16(a0), h1 = __float2bfloat16(a1);
        *(__nv_bfloat162*)(poh + d) = __halves2bfloat162(h0, h1);
        __nv_bfloat16 l0 = __float2bfloat16(a0 - __bfloat162float(h0));
        __nv_bfloat16 l1 = __float2bfloat16(a1 - __bfloat162float(h1));
        *(__nv_bfloat162*)(pol + d) = __halves2bfloat162(l0, l1);
    }
}

// ============================ launch =========================================
static void* symaddr_(const void* sym)
{
    void* p = nullptr;
    cudaGetSymbolAddress(&p, sym);
    return p;
}
#define SYM(T, name) T* name = (T*)symaddr_(g_##name)

extern "C" void kernel_launch(void* const* d_in, const int* in_sizes, int n_in,
                              void* d_out, int out_size)
{
    const float* x      = (const float*)d_in[0];
    const float* red_w  = (const float*)d_in[1];
    const float* red_b  = (const float*)d_in[2];
    const float* bn1_g  = (const float*)d_in[3];
    const float* bn1_b  = (const float*)d_in[4];
    const float* bn1_m  = (const float*)d_in[5];
    const float* bn1_v  = (const float*)d_in[6];
    const float* filt_w = (const float*)d_in[7];
    const float* filt_b = (const float*)d_in[8];
    const float* bn2_g  = (const float*)d_in[9];
    const float* bn2_b  = (const float*)d_in[10];
    const float* bn2_m  = (const float*)d_in[11];
    const float* bn2_v  = (const float*)d_in[12];
    const float* kvq_w  = (const float*)d_in[13];
    const float* kvq_b  = (const float*)d_in[14];
    const float* q_w    = (const float*)d_in[15];
    const float* q_b    = (const float*)d_in[16];
    const float* ln_g   = (const float*)d_in[17];
    const float* ln_b   = (const float*)d_in[18];
    const float* kv_w   = (const float*)d_in[19];
    const float* kv_b   = (const float*)d_in[20];
    const float* proj_w = (const float*)d_in[21];
    const float* proj_b = (const float*)d_in[22];

    float* out  = (float*)d_out;
    float* attn = out + OUT_ELEMS;

    SYM(float, q); SYM(float, xred); SYM(float, dwt2); SYM(float, kvtok); SYM(float, kv);
    SYM(float, sc1); SYM(float, sh1); SYM(float, sc2); SYM(float, sh2);
    SYM(__nv_bfloat16, xh);  SYM(__nv_bfloat16, xl);
    SYM(__nv_bfloat16, d1h); SYM(__nv_bfloat16, d1l);
    SYM(__nv_bfloat16, aph); SYM(__nv_bfloat16, apl);
    SYM(__nv_bfloat16, lnh); SYM(__nv_bfloat16, lnl);
    SYM(__nv_bfloat16, imh); SYM(__nv_bfloat16, iml);
    SYM(__nv_bfloat16, qwh); SYM(__nv_bfloat16, qwl);
    SYM(__nv_bfloat16, rwh); SYM(__nv_bfloat16, rwl);
    SYM(__nv_bfloat16, cwh); SYM(__nv_bfloat16, cwl);
    SYM(__nv_bfloat16, kqwh); SYM(__nv_bfloat16, kqwl);
    SYM(__nv_bfloat16, kvwh); SYM(__nv_bfloat16, kvwl);
    SYM(__nv_bfloat16, pwh); SYM(__nv_bfloat16, pwl);

    cudaFuncSetAttribute(tgemm_k<0, 0>, cudaFuncAttributeMaxDynamicSharedMemorySize, SMEM_DYN);
    cudaFuncSetAttribute(tgemm_k<1, 0>, cudaFuncAttributeMaxDynamicSharedMemorySize, SMEM_DYN);
    cudaFuncSetAttribute(tgemm_k<1, 1>, cudaFuncAttributeMaxDynamicSharedMemorySize, SMEM_DYN);

    // ---- prep (ordered so q-GEMM is launch #6 for the ncu -s 5 -c 1 window) ----
    bnprep_k<<<1, 128>>>(bn1_g, bn1_b, bn1_m, bn1_v, red_b, sc1, sh1, 128);        // 1
    bnprep_k<<<2, 256>>>(bn2_g, bn2_b, bn2_m, bn2_v, filt_b, sc2, sh2, 512);       // 2
    cvt_k<<<32768, 256>>>(x, xh, xl, 33554432);                                    // 3
    cvt_k<<<256, 256>>>(q_w, qwh, qwl, 262144);                                    // 4
    cvt_k<<<64, 256>>>(red_w, rwh, rwl, 65536);                                    // 5

    // ---- q = (x @ q_w^T + q_b) * 0.125 ----  (launch #6: profiled)
    tgemm_k<0, 0><<<dim3(4, 512), 256, SMEM_DYN>>>(xh, xl, qwh, qwl, q_b, nullptr, nullptr,
                                                   q, 65536, 512, 512, 0.125f);

    cvt_k<<<4096, 256>>>(kvq_w, kqwh, kqwl, 4194304);
    cvt_k<<<512, 256>>>(kv_w, kvwh, kvwl, 524288);
    cvt_k<<<320, 256>>>(proj_w, pwh, pwl, 327680);
    wremap_k<<<9216, 256>>>(filt_w, cwh, cwl);

    // ---- xred = relu(bn1(x @ red_w^T)) ----
    tgemm_k<1, 0><<<dim3(1, 512), 256, SMEM_DYN>>>(xh, xl, rwh, rwl, nullptr, sc1, sh1,
                                                   xred, 65536, 128, 512, 1.f);
    // ---- DWT -> bf16 pairs ----
    dwt_k<<<2048, 256>>>(xred, d1h, d1l);
    // ---- conv3x3 + bn2 + relu (implicit im2col) ----
    tgemm_k<1, 1><<<dim3(4, 128), 256, SMEM_DYN>>>(d1h, d1l, cwh, cwl, nullptr, sc2, sh2,
                                                   dwt2, 16384, 512, 4608, 1.f);
    // ---- IDWT -> aproj pairs cols [512,640) ----
    idwt_k<<<2048, 256>>>(dwt2, aph, apl);
    // ---- kvq conv via im2col ----
    im2col_k<<<8192, 256>>>(dwt2, imh, iml);
    tgemm_k<0, 0><<<dim3(4, 8), 256, SMEM_DYN>>>(imh, iml, kqwh, kqwl, kvq_b, nullptr, nullptr,
                                                 kvtok, 1024, 512, 8192, 1.f);
    // ---- layernorm + kv GEMM ----
    ln_k<<<1024, 256>>>(kvtok, ln_g, ln_b, lnh, lnl);
    tgemm_k<0, 0><<<dim3(8, 8), 256, SMEM_DYN>>>(lnh, lnl, kvwh, kvwl, kv_b, nullptr, nullptr,
                                                 kv, 1024, 1024, 512, 1.f);
    // ---- attention: attn output + aproj pairs cols [0,512) ----
    attn_k<<<dim3(128, 32), 128>>>(q, kv, attn, aph, apl);
    // ---- proj ----
    tgemm_k<0, 0><<<dim3(4, 512), 256, SMEM_DYN>>>(aph, apl, pwh, pwl, proj_b, nullptr, nullptr,
                                                   out, 65536, 512, 640, 1.f);
}

// round 6
// speedup vs baseline: 2.4049x; 1.0783x over previous
#include <cuda_runtime.h>
#include <cuda_bf16.h>
#include <cstdint>
#include <math.h>

// ============================ PTX helpers (sm_80+ path) =====================
__device__ __forceinline__ uint32_t smem_u32(const void* p) {
    uint32_t a;
    asm("{ .reg .u64 t; cvta.to.shared.u64 t, %1; cvt.u32.u64 %0, t; }" : "=r"(a) : "l"(p));
    return a;
}
__device__ __forceinline__ void cp16(uint32_t dst, const void* src, int pred) {
    asm volatile("cp.async.cg.shared.global [%0], [%1], 16, %2;"
                 :: "r"(dst), "l"(src), "r"(pred ? 16 : 0) : "memory");
}
__device__ __forceinline__ void ldmx4(uint32_t* r, uint32_t addr) {
    asm volatile("ldmatrix.sync.aligned.m8n8.x4.shared.b16 {%0,%1,%2,%3}, [%4];"
                 : "=r"(r[0]), "=r"(r[1]), "=r"(r[2]), "=r"(r[3]) : "r"(addr));
}
__device__ __forceinline__ void hmma(float* d, const uint32_t* a, const uint32_t* b) {
    asm volatile("mma.sync.aligned.m16n8k16.row.col.f32.bf16.bf16.f32 "
                 "{%0,%1,%2,%3}, {%4,%5,%6,%7}, {%8,%9}, {%0,%1,%2,%3};"
                 : "+f"(d[0]), "+f"(d[1]), "+f"(d[2]), "+f"(d[3])
                 : "r"(a[0]), "r"(a[1]), "r"(a[2]), "r"(a[3]), "r"(b[0]), "r"(b[1]));
}

// ============================ scratch ============================
#define OUT_ELEMS 33554432
static __device__ float g_q[33554432];
static __device__ float g_xred[8388608];
static __device__ float g_dwt2[8388608];
static __device__ float g_kvtok[524288];
static __device__ float g_kv[1048576];
static __device__ float g_sc1[128], g_sh1[128], g_sc2[512], g_sh2[512];

static __device__ __nv_bfloat16 g_xh[33554432], g_xl[33554432];
static __device__ __nv_bfloat16 g_d1h[8388608],  g_d1l[8388608];
static __device__ __nv_bfloat16 g_aph[41943040], g_apl[41943040];
static __device__ __nv_bfloat16 g_lnh[524288],   g_lnl[524288];
static __device__ __nv_bfloat16 g_imh[8388608],  g_iml[8388608];
static __device__ __nv_bfloat16 g_qwh[262144],   g_qwl[262144];
static __device__ __nv_bfloat16 g_rwh[65536],    g_rwl[65536];
static __device__ __nv_bfloat16 g_cwh[2359296],  g_cwl[2359296];
static __device__ __nv_bfloat16 g_kqwh[4194304], g_kqwl[4194304];
static __device__ __nv_bfloat16 g_kvwh[524288],  g_kvwl[524288];
static __device__ __nv_bfloat16 g_pwh[327680],   g_pwl[327680];

// ============================ small helpers ============================
__device__ __forceinline__ void store_pair4(__nv_bfloat16* ph, __nv_bfloat16* pl, float4 v)
{
    __nv_bfloat16 hx = __float2bfloat16(v.x), hy = __float2bfloat16(v.y);
    __nv_bfloat16 hz = __float2bfloat16(v.z), hw = __float2bfloat16(v.w);
    ((__nv_bfloat162*)ph)[0] = __halves2bfloat162(hx, hy);
    ((__nv_bfloat162*)ph)[1] = __halves2bfloat162(hz, hw);
    __nv_bfloat16 lx = __float2bfloat16(v.x - __bfloat162float(hx));
    __nv_bfloat16 ly = __float2bfloat16(v.y - __bfloat162float(hy));
    __nv_bfloat16 lz = __float2bfloat16(v.z - __bfloat162float(hz));
    __nv_bfloat16 lw = __float2bfloat16(v.w - __bfloat162float(hw));
    ((__nv_bfloat162*)pl)[0] = __halves2bfloat162(lx, ly);
    ((__nv_bfloat162*)pl)[1] = __halves2bfloat162(lz, lw);
}

__global__ void cvt_k(const float* __restrict__ in, __nv_bfloat16* __restrict__ h,
                      __nv_bfloat16* __restrict__ l, int n)
{
    int i = (blockIdx.x * 256 + threadIdx.x) * 4;
    if (i >= n) return;
    store_pair4(h + i, l + i, *(const float4*)(in + i));
}

__global__ void bnprep_k(const float* __restrict__ g, const float* __restrict__ be,
                         const float* __restrict__ mu, const float* __restrict__ va,
                         const float* __restrict__ bias, float* __restrict__ sc,
                         float* __restrict__ sh, int n)
{
    int i = blockIdx.x * blockDim.x + threadIdx.x;
    if (i < n) {
        float s = g[i] * rsqrtf(va[i] + 1e-5f);
        sc[i] = s;
        sh[i] = be[i] - mu[i] * s + bias[i] * s;
    }
}

// filt_w (o,c,3,3) -> (o, tap*512+c), split into bf16 pairs
__global__ void wremap_k(const float* __restrict__ fw, __nv_bfloat16* __restrict__ wh,
                         __nv_bfloat16* __restrict__ wl)
{
    int idx = blockIdx.x * 256 + threadIdx.x;
    if (idx >= 512 * 4608) return;
    int o = idx / 4608;
    int k = idx - o * 4608;
    int tap = k >> 9, c = k & 511;
    float v = fw[o * 4608 + c * 9 + tap];
    __nv_bfloat16 h = __float2bfloat16(v);
    wh[idx] = h;
    wl[idx] = __float2bfloat16(v - __bfloat162float(h));
}

// ============================ tensor-core GEMM (mma.sync bf16 split) =========
// C[M,N] = epi(A[M,K] @ B[N,K]^T), A/B as bf16 (hi,lo) pairs; 3-product split.
// CTA tile 128x128, BK=64, 3-stage cp.async pipeline (fill 2 ahead),
// ONE __syncthreads per chunk. 8 warps, warp tile 64x32. 1 CTA/SM, no reg cap.
// EPI 0: alpha*(acc+bias[n]);  EPI 1: relu(acc*sc[n]+sh[n])
// CONV 1: A gathered implicitly from (B,32,32,512) with 3x3 pad-1 taps.
#define ROW_B 144               // 64 bf16 = 128B + 16B pad (4-bank step)
#define TILE_B (128 * ROW_B)    // 18432
#define STAGE_B (4 * TILE_B)    // 73728: Ah, Al, Bh, Bl
#define SMEM_DYN (3 * STAGE_B)  // 221184

template<int EPI, int CONV>
__global__ void __launch_bounds__(256, 1)
tgemm_k(const __nv_bfloat16* __restrict__ Ah, const __nv_bfloat16* __restrict__ Al,
        const __nv_bfloat16* __restrict__ Bh, const __nv_bfloat16* __restrict__ Bl,
        const float* __restrict__ bias, const float* __restrict__ sc,
        const float* __restrict__ sh, float* __restrict__ C,
        int M, int N, int K, float alpha)
{
    extern __shared__ char smem[];
    const uint32_t sbase = smem_u32(smem);
    const int tid = threadIdx.x;
    const int wid = tid >> 5;
    const int lane = tid & 31;
    const int wm = wid >> 2;
    const int wn = wid & 3;
    const int bm = blockIdx.y << 7;
    const int bn = blockIdx.x << 7;

    const int nc = K >> 6;   // 64-wide K chunks

    float acc[4][4][4];
#pragma unroll
    for (int i = 0; i < 4; i++)
#pragma unroll
        for (int j = 0; j < 4; j++)
#pragma unroll
            for (int r = 0; r < 4; r++) acc[i][j][r] = 0.f;

    auto fill = [&](int stage, int k0) {
        uint32_t sb = sbase + stage * STAGE_B;
#pragma unroll
        for (int it = 0; it < 16; it++) {
            int g = it * 256 + tid;
            int t = g >> 10;          // 0=Ah 1=Al 2=Bh 3=Bl
            int s = g & 1023;
            int r = s >> 3;
            int c8 = s & 7;           // 8-elem (16B) column group
            uint32_t dst = sb + t * TILE_B + r * ROW_B + c8 * 16;
            if (t >= 2) {
                const __nv_bfloat16* src = (t == 2 ? Bh : Bl) + (long)(bn + r) * K + k0 + c8 * 8;
                cp16(dst, src, 1);
            } else if (!CONV) {
                const __nv_bfloat16* src = (t == 0 ? Ah : Ah == Al ? Al : Al) + 0;
                src = (t == 0 ? Ah : Al) + (long)(bm + r) * K + k0 + c8 * 8;
                cp16(dst, src, 1);
            } else {
                int m = bm + r;
                int cb = m >> 10, p = m & 1023, cy = p >> 5, cx = p & 31;
                int tap = k0 >> 9;
                int dy = tap / 3 - 1, dx = tap - (tap / 3) * 3 - 1;
                int yy = cy + dy, xx = cx + dx;
                int pred = ((unsigned)yy < 32u) && ((unsigned)xx < 32u);
                long off = pred ? (((long)((cb * 32 + yy) * 32 + xx)) << 9) + (k0 & 511) + c8 * 8 : 0;
                const __nv_bfloat16* src = (t == 0 ? Ah : Al) + off;
                cp16(dst, src, pred);
            }
        }
    };

    // prologue: 2 stages in flight
    fill(0, 0);
    asm volatile("cp.async.commit_group;" ::: "memory");
    if (nc > 1) fill(1, 64);
    asm volatile("cp.async.commit_group;" ::: "memory");

    const int a_row = (lane & 15);
    const int a_kof = (lane >> 4) << 3;                 // 0/8 elems
    const int b_row = (lane & 7) + ((lane >> 4) << 3);
    const int b_kof = ((lane >> 3) & 1) << 3;

    int stage = 0;
    for (int c = 0; c < nc; c++) {
        asm volatile("cp.async.wait_group 1;" ::: "memory");
        __syncthreads();
        uint32_t sb = sbase + stage * STAGE_B;
        uint32_t pAh = sb + (wm * 64 + a_row) * ROW_B + a_kof * 2;
        uint32_t pAl = pAh + TILE_B;
        uint32_t pBh = sb + 2 * TILE_B + (wn * 32 + b_row) * ROW_B + b_kof * 2;
        uint32_t pBl = pBh + TILE_B;

#pragma unroll
        for (int ks = 0; ks < 4; ks++) {
            uint32_t ah[4][4], al[4][4], bh[2][4], bl[2][4];
#pragma unroll
            for (int mi = 0; mi < 4; mi++) {
                ldmx4(ah[mi], pAh + mi * 16 * ROW_B + ks * 32);
                ldmx4(al[mi], pAl + mi * 16 * ROW_B + ks * 32);
            }
#pragma unroll
            for (int nj = 0; nj < 2; nj++) {
                ldmx4(bh[nj], pBh + nj * 16 * ROW_B + ks * 32);
                ldmx4(bl[nj], pBl + nj * 16 * ROW_B + ks * 32);
            }
#pragma unroll
            for (int mi = 0; mi < 4; mi++)
#pragma unroll
                for (int ni = 0; ni < 4; ni++) {
                    const uint32_t* bhp = &bh[ni >> 1][(ni & 1) * 2];
                    const uint32_t* blp = &bl[ni >> 1][(ni & 1) * 2];
                    hmma(acc[mi][ni], ah[mi], bhp);
                    hmma(acc[mi][ni], ah[mi], blp);
                    hmma(acc[mi][ni], al[mi], bhp);
                }
        }
        // fill 2 ahead into stage (c+2)%3 — not read until iter c+2, and its
        // previous readers (iter c-1) are past the sync above.
        if (c + 2 < nc) {
            int fs = stage + 2; if (fs >= 3) fs -= 3;
            fill(fs, (c + 2) << 6);
        }
        asm volatile("cp.async.commit_group;" ::: "memory");
        if (++stage == 3) stage = 0;
    }

    // epilogue
#pragma unroll
    for (int mi = 0; mi < 4; mi++) {
#pragma unroll
        for (int ni = 0; ni < 4; ni++) {
            int row = bm + wm * 64 + mi * 16 + (lane >> 2);
            int col = bn + wn * 32 + ni * 8 + (lane & 3) * 2;
            float2 e0, e1;
            if (EPI == 0) {
                float2 bv = *(const float2*)(bias + col);
                e0.x = alpha * (acc[mi][ni][0] + bv.x);
                e0.y = alpha * (acc[mi][ni][1] + bv.y);
                e1.x = alpha * (acc[mi][ni][2] + bv.x);
                e1.y = alpha * (acc[mi][ni][3] + bv.y);
            } else {
                float2 sv = *(const float2*)(sc + col);
                float2 hv = *(const float2*)(sh + col);
                e0.x = fmaxf(acc[mi][ni][0] * sv.x + hv.x, 0.f);
                e0.y = fmaxf(acc[mi][ni][1] * sv.y + hv.y, 0.f);
                e1.x = fmaxf(acc[mi][ni][2] * sv.x + hv.x, 0.f);
                e1.y = fmaxf(acc[mi][ni][3] * sv.y + hv.y, 0.f);
            }
            *(float2*)(C + (long)row * N + col) = e0;
            *(float2*)(C + (long)(row + 8) * N + col) = e1;
        }
    }
}

// ---------------- Haar DWT ----------------------------------------------------
__global__ void dwt_k(const float* __restrict__ xr, __nv_bfloat16* __restrict__ oh,
                      __nv_bfloat16* __restrict__ ol)
{
    int idx = blockIdx.x * 256 + threadIdx.x;
    int cq = idx & 31;
    int pos = idx >> 5;
    int b = pos >> 10;
    int r = pos & 1023;
    int h = r >> 5, w = r & 31;
    const float* base = xr + ((long)((b * 64 + 2 * h) * 64 + 2 * w)) * 128 + cq * 4;
    float4 x00 = *(const float4*)(base);
    float4 x01 = *(const float4*)(base + 128);
    float4 x10 = *(const float4*)(base + 64 * 128);
    float4 x11 = *(const float4*)(base + 64 * 128 + 128);
    float4 ll, lh, hl, hh;
#define DWT1(f) \
    ll.f = 0.5f * (x00.f + x01.f + x10.f + x11.f); \
    lh.f = 0.5f * (x00.f + x01.f - x10.f - x11.f); \
    hl.f = 0.5f * (x00.f - x01.f + x10.f - x11.f); \
    hh.f = 0.5f * (x00.f - x01.f - x10.f + x11.f);
    DWT1(x) DWT1(y) DWT1(z) DWT1(w)
#undef DWT1
    long o = (long)pos * 512 + cq * 4;
    store_pair4(oh + o,       ol + o,       ll);
    store_pair4(oh + o + 128, ol + o + 128, lh);
    store_pair4(oh + o + 256, ol + o + 256, hl);
    store_pair4(oh + o + 384, ol + o + 384, hh);
}

// ---------------- Haar IDWT ----------------------------------------------------
__global__ void idwt_k(const float* __restrict__ d2, __nv_bfloat16* __restrict__ aph,
                       __nv_bfloat16* __restrict__ apl)
{
    int idx = blockIdx.x * 256 + threadIdx.x;
    int cq = idx & 31;
    int pos = idx >> 5;
    int b = pos >> 10;
    int r = pos & 1023;
    int h = r >> 5, w = r & 31;
    const float* ip = d2 + (long)pos * 512 + cq * 4;
    float4 ll = *(const float4*)(ip);
    float4 lh = *(const float4*)(ip + 128);
    float4 hl = *(const float4*)(ip + 256);
    float4 hh = *(const float4*)(ip + 384);
    float4 y00, y01, y10, y11;
#define IDWT1(f) \
    y00.f = 0.5f * (ll.f + lh.f + hl.f + hh.f); \
    y01.f = 0.5f * (ll.f + lh.f - hl.f - hh.f); \
    y10.f = 0.5f * (ll.f - lh.f + hl.f - hh.f); \
    y11.f = 0.5f * (ll.f - lh.f - hl.f + hh.f);
    IDWT1(x) IDWT1(y) IDWT1(z) IDWT1(w)
#undef IDWT1
    long base = ((long)(b * 4096 + (2 * h) * 64 + 2 * w)) * 640 + 512 + cq * 4;
    store_pair4(aph + base,                apl + base,                y00);
    store_pair4(aph + base + 640,          apl + base + 640,          y01);
    store_pair4(aph + base + 64 * 640,       apl + base + 64 * 640,       y10);
    store_pair4(aph + base + 64 * 640 + 640, apl + base + 64 * 640 + 640, y11);
}

// ---------------- im2col for kvq conv ----------------------------------------
__global__ void im2col_k(const float* __restrict__ d2, __nv_bfloat16* __restrict__ ch,
                         __nv_bfloat16* __restrict__ cl)
{
    int idx = blockIdx.x * 256 + threadIdx.x;
    if (idx >= 1024 * 2048) return;
    int t = idx >> 11;
    int k4 = (idx & 2047) * 4;
    int c = k4 >> 4;
    int ij = k4 & 15;
    int i = ij >> 2;
    int b = t >> 6;
    int pp = t & 63;
    int ph = pp >> 3, pw = pp & 7;
    int y = 4 * ph + i;
    int x0 = 4 * pw;
    const float* sp = d2 + ((long)((b * 32 + y) * 32 + x0)) * 512 + c;
    float4 v;
    v.x = sp[0]; v.y = sp[512]; v.z = sp[1024]; v.w = sp[1536];
    store_pair4(ch + (long)t * 8192 + k4, cl + (long)t * 8192 + k4, v);
}

// ---------------- layernorm -> bf16 pairs ------------------------------------
__global__ void ln_k(const float* __restrict__ in, const float* __restrict__ g,
                     const float* __restrict__ be, __nv_bfloat16* __restrict__ oh,
                     __nv_bfloat16* __restrict__ ol)
{
    int row = blockIdx.x;
    const float* p = in + (long)row * 512;
    int tid = threadIdx.x;
    float x0 = p[tid], x1 = p[tid + 256];
    float s = x0 + x1, q = x0 * x0 + x1 * x1;
    __shared__ float red[16];
    __shared__ float mv[2];
#pragma unroll
    for (int o = 16; o; o >>= 1) {
        s += __shfl_down_sync(0xffffffffu, s, o);
        q += __shfl_down_sync(0xffffffffu, q, o);
    }
    if ((tid & 31) == 0) { red[tid >> 5] = s; red[8 + (tid >> 5)] = q; }
    __syncthreads();
    if (tid == 0) {
        float S = 0.f, Q = 0.f;
        for (int i = 0; i < 8; i++) { S += red[i]; Q += red[8 + i]; }
        float mean = S * (1.f / 512.f);
        float var = Q * (1.f / 512.f) - mean * mean;
        mv[0] = mean;
        mv[1] = rsqrtf(var + 1e-5f);
    }
    __syncthreads();
    float mean = mv[0], inv = mv[1];
    float v0 = (x0 - mean) * inv * g[tid] + be[tid];
    float v1 = (x1 - mean) * inv * g[tid + 256] + be[tid + 256];
    __nv_bfloat16 h0 = __float2bfloat16(v0), h1 = __float2bfloat16(v1);
    oh[(long)row * 512 + tid] = h0;
    oh[(long)row * 512 + tid + 256] = h1;
    ol[(long)row * 512 + tid] = __float2bfloat16(v0 - __bfloat162float(h0));
    ol[(long)row * 512 + tid + 256] = __float2bfloat16(v1 - __bfloat162float(h1));
}

// ---------------- attention: Lk=64 -------------------------------------------
__global__ void __launch_bounds__(128)
attn_k(const float* __restrict__ qbuf, const float* __restrict__ kv,
       float* __restrict__ attn_out, __nv_bfloat16* __restrict__ aph,
       __nv_bfloat16* __restrict__ apl)
{
    __shared__ float ks[64][65];
    __shared__ float vs[64][65];
    int b = blockIdx.x >> 3;
    int h = blockIdx.x & 7;
    int tid = threadIdx.x;
    for (int i = tid; i < 64 * 64; i += 128) {
        int t = i >> 6, d = i & 63;
        const float* kr = kv + (long)(b * 64 + t) * 1024 + h * 64;
        ks[t][d] = kr[d];
        vs[t][d] = kr[512 + d];
    }
    __syncthreads();
    int l = blockIdx.y * 128 + tid;
    long m = (long)b * 4096 + l;
    const float* qp = qbuf + m * 512 + h * 64;
    float qr[64];
#pragma unroll
    for (int d = 0; d < 64; d++) qr[d] = qp[d];
    float s[64];
    float mx = -1e30f;
#pragma unroll
    for (int j = 0; j < 64; j++) {
        float a = 0.f;
#pragma unroll
        for (int d = 0; d < 64; d++) a = fmaf(qr[d], ks[j][d], a);
        s[j] = a;
        mx = fmaxf(mx, a);
    }
    float sum = 0.f;
#pragma unroll
    for (int j = 0; j < 64; j++) { s[j] = __expf(s[j] - mx); sum += s[j]; }
    float inv = 1.f / sum;
    float* ao = attn_out + (((long)(b * 8 + h) * 4096 + l) << 6);
#pragma unroll
    for (int j = 0; j < 64; j++) { s[j] *= inv; ao[j] = s[j]; }
    __nv_bfloat16* poh = aph + m * 640 + h * 64;
    __nv_bfloat16* pol = apl + m * 640 + h * 64;
#pragma unroll
    for (int d = 0; d < 64; d += 2) {
        float a0 = 0.f, a1 = 0.f;
#pragma unroll
        for (int j = 0; j < 64; j++) {
            a0 = fmaf(s[j], vs[j][d], a0);
            a1 = fmaf(s[j], vs[j][d + 1], a1);
        }
        __nv_bfloat16 h0 = __float2bfloat16(a0), h1 = __float2bfloat16(a1);
        *(__nv_bfloat162*)(poh + d) = __halves2bfloat162(h0, h1);
        __nv_bfloat16 l0 = __float2bfloat16(a0 - __bfloat162float(h0));
        __nv_bfloat16 l1 = __float2bfloat16(a1 - __bfloat162float(h1));
        *(__nv_bfloat162*)(pol + d) = __halves2bfloat162(l0, l1);
    }
}

// ============================ launch =========================================
static void* symaddr_(const void* sym)
{
    void* p = nullptr;
    cudaGetSymbolAddress(&p, sym);
    return p;
}
#define SYM(T, name) T* name = (T*)symaddr_(g_##name)

extern "C" void kernel_launch(void* const* d_in, const int* in_sizes, int n_in,
                              void* d_out, int out_size)
{
    const float* x      = (const float*)d_in[0];
    const float* red_w  = (const float*)d_in[1];
    const float* red_b  = (const float*)d_in[2];
    const float* bn1_g  = (const float*)d_in[3];
    const float* bn1_b  = (const float*)d_in[4];
    const float* bn1_m  = (const float*)d_in[5];
    const float* bn1_v  = (const float*)d_in[6];
    const float* filt_w = (const float*)d_in[7];
    const float* filt_b = (const float*)d_in[8];
    const float* bn2_g  = (const float*)d_in[9];
    const float* bn2_b  = (const float*)d_in[10];
    const float* bn2_m  = (const float*)d_in[11];
    const float* bn2_v  = (const float*)d_in[12];
    const float* kvq_w  = (const float*)d_in[13];
    const float* kvq_b  = (const float*)d_in[14];
    const float* q_w    = (const float*)d_in[15];
    const float* q_b    = (const float*)d_in[16];
    const float* ln_g   = (const float*)d_in[17];
    const float* ln_b   = (const float*)d_in[18];
    const float* kv_w   = (const float*)d_in[19];
    const float* kv_b   = (const float*)d_in[20];
    const float* proj_w = (const float*)d_in[21];
    const float* proj_b = (const float*)d_in[22];

    float* out  = (float*)d_out;
    float* attn = out + OUT_ELEMS;

    SYM(float, q); SYM(float, xred); SYM(float, dwt2); SYM(float, kvtok); SYM(float, kv);
    SYM(float, sc1); SYM(float, sh1); SYM(float, sc2); SYM(float, sh2);
    SYM(__nv_bfloat16, xh);  SYM(__nv_bfloat16, xl);
    SYM(__nv_bfloat16, d1h); SYM(__nv_bfloat16, d1l);
    SYM(__nv_bfloat16, aph); SYM(__nv_bfloat16, apl);
    SYM(__nv_bfloat16, lnh); SYM(__nv_bfloat16, lnl);
    SYM(__nv_bfloat16, imh); SYM(__nv_bfloat16, iml);
    SYM(__nv_bfloat16, qwh); SYM(__nv_bfloat16, qwl);
    SYM(__nv_bfloat16, rwh); SYM(__nv_bfloat16, rwl);
    SYM(__nv_bfloat16, cwh); SYM(__nv_bfloat16, cwl);
    SYM(__nv_bfloat16, kqwh); SYM(__nv_bfloat16, kqwl);
    SYM(__nv_bfloat16, kvwh); SYM(__nv_bfloat16, kvwl);
    SYM(__nv_bfloat16, pwh); SYM(__nv_bfloat16, pwl);

    cudaFuncSetAttribute(tgemm_k<0, 0>, cudaFuncAttributeMaxDynamicSharedMemorySize, SMEM_DYN);
    cudaFuncSetAttribute(tgemm_k<1, 0>, cudaFuncAttributeMaxDynamicSharedMemorySize, SMEM_DYN);
    cudaFuncSetAttribute(tgemm_k<1, 1>, cudaFuncAttributeMaxDynamicSharedMemorySize, SMEM_DYN);

    // ---- prep (q-GEMM kept as launch #6 for the ncu window) ----
    bnprep_k<<<1, 128>>>(bn1_g, bn1_b, bn1_m, bn1_v, red_b, sc1, sh1, 128);        // 1
    bnprep_k<<<2, 256>>>(bn2_g, bn2_b, bn2_m, bn2_v, filt_b, sc2, sh2, 512);       // 2
    cvt_k<<<32768, 256>>>(x, xh, xl, 33554432);                                    // 3
    cvt_k<<<256, 256>>>(q_w, qwh, qwl, 262144);                                    // 4
    cvt_k<<<64, 256>>>(red_w, rwh, rwl, 65536);                                    // 5

    // ---- q = (x @ q_w^T + q_b) * 0.125 ----  (launch #6)
    tgemm_k<0, 0><<<dim3(4, 512), 256, SMEM_DYN>>>(xh, xl, qwh, qwl, q_b, nullptr, nullptr,
                                                   q, 65536, 512, 512, 0.125f);

    cvt_k<<<4096, 256>>>(kvq_w, kqwh, kqwl, 4194304);
    cvt_k<<<512, 256>>>(kv_w, kvwh, kvwl, 524288);
    cvt_k<<<320, 256>>>(proj_w, pwh, pwl, 327680);
    wremap_k<<<9216, 256>>>(filt_w, cwh, cwl);

    // ---- xred = relu(bn1(x @ red_w^T)) ----
    tgemm_k<1, 0><<<dim3(1, 512), 256, SMEM_DYN>>>(xh, xl, rwh, rwl, nullptr, sc1, sh1,
                                                   xred, 65536, 128, 512, 1.f);
    // ---- DWT -> bf16 pairs ----
    dwt_k<<<2048, 256>>>(xred, d1h, d1l);
    // ---- conv3x3 + bn2 + relu (implicit im2col) ----
    tgemm_k<1, 1><<<dim3(4, 128), 256, SMEM_DYN>>>(d1h, d1l, cwh, cwl, nullptr, sc2, sh2,
                                                   dwt2, 16384, 512, 4608, 1.f);
    // ---- IDWT -> aproj pairs cols [512,640) ----
    idwt_k<<<2048, 256>>>(dwt2, aph, apl);
    // ---- kvq conv via im2col ----
    im2col_k<<<8192, 256>>>(dwt2, imh, iml);
    tgemm_k<0, 0><<<dim3(4, 8), 256, SMEM_DYN>>>(imh, iml, kqwh, kqwl, kvq_b, nullptr, nullptr,
                                                 kvtok, 1024, 512, 8192, 1.f);
    // ---- layernorm + kv GEMM ----
    ln_k<<<1024, 256>>>(kvtok, ln_g, ln_b, lnh, lnl);
    tgemm_k<0, 0><<<dim3(8, 8), 256, SMEM_DYN>>>(lnh, lnl, kvwh, kvwl, kv_b, nullptr, nullptr,
                                                 kv, 1024, 1024, 512, 1.f);
    // ---- attention: attn output + aproj pairs cols [0,512) ----
    attn_k<<<dim3(128, 32), 128>>>(q, kv, attn, aph, apl);
    // ---- proj ----
    tgemm_k<0, 0><<<dim3(4, 512), 256, SMEM_DYN>>>(aph, apl, pwh, pwl, proj_b, nullptr, nullptr,
                                                   out, 65536, 512, 640, 1.f);
}